// round 3
// baseline (speedup 1.0000x reference)
#include <cuda_runtime.h>
#include <cstdint>

// ---------------- problem constants ----------------
#define BATCH 16
#define DIM   64
#define KNUM  4
#define HW    256
#define KS    5
#define HOUT  127          // (256 + 2 - 5)/2 + 1
#define HWOUT (HOUT*HOUT)  // 16129

// conv tiling
#define OBLK  16           // output channels per block
#define ICB   4            // input channels per smem chunk
#define TH    16           // output rows per tile
#define TW    32           // output cols per tile
#define XROWS 35           // (TH-1)*2 + 5
#define XCOLS 67           // (TW-1)*2 + 5
#define XPITCH 68

// ---------------- device scratch (no allocs allowed) ----------------
__device__ float g_pooled[BATCH * DIM];              // (B, C)
__device__ float g_att[BATCH * KNUM];                // (B, K)
__device__ float g_aggb[BATCH * DIM];                // (B, Cout)
__device__ float g_aggw[BATCH * DIM * DIM * KS*KS];  // (B, Cout, Cin, 25) = 1,638,400

// ---------------- kernel 1: global average pool ----------------
__global__ void pool_kernel(const float* __restrict__ x) {
    int bc = blockIdx.x;                         // 0..1023
    const float4* p = (const float4*)(x + (size_t)bc * (HW*HW));
    float s = 0.f;
    for (int i = threadIdx.x; i < (HW*HW)/4; i += 256) {
        float4 v = p[i];
        s += (v.x + v.y) + (v.z + v.w);
    }
    __shared__ float sm[256];
    sm[threadIdx.x] = s;
    __syncthreads();
    for (int off = 128; off > 0; off >>= 1) {
        if (threadIdx.x < off) sm[threadIdx.x] += sm[threadIdx.x + off];
        __syncthreads();
    }
    if (threadIdx.x == 0) g_pooled[bc] = sm[0] * (1.0f / (HW*HW));
}

// ---------------- kernel 2: attention (fc1-relu-fc2-softmax) + agg_b ----------------
__global__ void att_kernel(const float* __restrict__ fc1_w, const float* __restrict__ fc1_b,
                           const float* __restrict__ fc2_w, const float* __restrict__ fc2_b,
                           const float* __restrict__ bias) {
    __shared__ float att_s[BATCH][KNUM];
    int t = threadIdx.x;
    if (t < BATCH) {
        float a[KNUM];
        #pragma unroll
        for (int k = 0; k < KNUM; k++) {
            float s = fc1_b[k];
            for (int c = 0; c < DIM; c++) s += g_pooled[t * DIM + c] * fc1_w[k * DIM + c];
            a[k] = s > 0.f ? s : 0.f;
        }
        float l[KNUM], mx = -1e30f;
        #pragma unroll
        for (int k = 0; k < KNUM; k++) {
            float s = fc2_b[k];
            #pragma unroll
            for (int j = 0; j < KNUM; j++) s += a[j] * fc2_w[k * KNUM + j];
            l[k] = s;
            mx = fmaxf(mx, s);
        }
        float den = 0.f;
        #pragma unroll
        for (int k = 0; k < KNUM; k++) { l[k] = __expf(l[k] - mx); den += l[k]; }
        float inv = 1.0f / den;
        #pragma unroll
        for (int k = 0; k < KNUM; k++) {
            float v = l[k] * inv;
            att_s[t][k] = v;
            g_att[t * KNUM + k] = v;
        }
    }
    __syncthreads();
    for (int idx = t; idx < BATCH * DIM; idx += blockDim.x) {
        int b = idx / DIM, o = idx % DIM;
        float s = 0.f;
        #pragma unroll
        for (int k = 0; k < KNUM; k++) s += att_s[b][k] * bias[k * DIM + o];
        g_aggb[idx] = s;
    }
}

// ---------------- kernel 3: agg_w mix + w_ret output ----------------
// agg_w[b, o, i, p] = sum_k att[b,k] * weight[k, o, i, p]
// w_ret[(b*64+o), p, i] = agg_w[b, o, i, p]
__global__ void aggw_kernel(const float* __restrict__ weight, float* __restrict__ wret) {
    const int PER_B = DIM * DIM * KS * KS;   // 102400
    int b = blockIdx.y;
    float a0 = g_att[b * 4 + 0], a1 = g_att[b * 4 + 1];
    float a2 = g_att[b * 4 + 2], a3 = g_att[b * 4 + 3];
    for (int j = blockIdx.x * blockDim.x + threadIdx.x; j < PER_B;
         j += gridDim.x * blockDim.x) {
        float v = a0 * weight[j]
                + a1 * weight[PER_B + j]
                + a2 * weight[2 * PER_B + j]
                + a3 * weight[3 * PER_B + j];
        g_aggw[(size_t)b * PER_B + j] = v;
        int o = j / (DIM * KS * KS);
        int r = j % (DIM * KS * KS);
        int i = r / (KS * KS);
        int p = r % (KS * KS);
        wret[(((size_t)b * DIM + o) * (KS * KS) + p) * DIM + i] = v;
    }
}

// ---------------- kernel 4: per-sample conv ----------------
// Block: (tileIdx, ogroup, b). Tile = TH x TW out pixels, OBLK out channels.
// 128 threads, each computes 2x2 pixels x 16 oc = 64 accs (as 32 f32x2 pairs).
#define FMA_F32X2(d, a, bb) asm("fma.rn.f32x2 %0, %1, %2, %0;" : "+l"(d) : "l"(a), "l"(bb))

__global__ __launch_bounds__(128) void conv_kernel(const float* __restrict__ x,
                                                   float* __restrict__ out) {
    __shared__ float xs[ICB][XROWS][XPITCH];            // 38,080 B
    __shared__ float ws[ICB][KS * KS][OBLK];            //  6,400 B

    const int b = blockIdx.z;
    const int og = blockIdx.y;                          // 0..3
    const int tileY = blockIdx.x / 4;                   // 8 row tiles
    const int tileX = blockIdx.x % 4;                   // 4 col tiles
    const int ho0 = tileY * TH, wo0 = tileX * TW;
    const int ih0 = ho0 * 2 - 1, iw0 = wo0 * 2 - 1;

    const int t = threadIdx.x;
    const int ty = t / 16;                              // 0..7
    const int tx = t % 16;                              // 0..15

    unsigned long long acc2[32];
    #pragma unroll
    for (int j = 0; j < 32; j++) acc2[j] = 0ULL;

    const float* xb = x + (size_t)b * DIM * (HW * HW);
    const float* wb = g_aggw + (size_t)b * (DIM * DIM * KS * KS)
                    + (size_t)(og * OBLK) * (DIM * KS * KS);

    for (int ic0 = 0; ic0 < DIM; ic0 += ICB) {
        // stage x tile: ICB * 35 * 67 elems
        for (int idx = t; idx < ICB * XROWS * XCOLS; idx += 128) {
            int i  = idx / (XROWS * XCOLS);
            int rr = (idx / XCOLS) % XROWS;
            int cc = idx % XCOLS;
            int ih = ih0 + rr, iw = iw0 + cc;
            float v = 0.f;
            if (ih >= 0 && ih < HW && iw >= 0 && iw < HW)
                v = xb[(size_t)(ic0 + i) * (HW * HW) + ih * HW + iw];
            xs[i][rr][cc] = v;
        }
        // stage weights: ICB * 25 * 16
        for (int idx = t; idx < ICB * KS * KS * OBLK; idx += 128) {
            int i = idx / (KS * KS * OBLK);
            int rem = idx % (KS * KS * OBLK);
            int p = rem / OBLK;
            int o = rem % OBLK;
            ws[i][p][o] = wb[(size_t)o * (DIM * KS * KS) + (ic0 + i) * (KS * KS) + p];
        }
        __syncthreads();

        for (int i = 0; i < ICB; i++) {
            #pragma unroll
            for (int kh = 0; kh < KS; kh++) {
                #pragma unroll
                for (int kw = 0; kw < KS; kw++) {
                    const int p = kh * KS + kw;
                    const unsigned long long* wp =
                        (const unsigned long long*)&ws[i][p][0];
                    unsigned long long w0 = wp[0], w1 = wp[1], w2 = wp[2], w3 = wp[3];
                    unsigned long long w4 = wp[4], w5 = wp[5], w6 = wp[6], w7 = wp[7];
                    #pragma unroll
                    for (int sy = 0; sy < 2; sy++) {
                        #pragma unroll
                        for (int sx = 0; sx < 2; sx++) {
                            float xv = xs[i][(ty + sy * 8) * 2 + kh]
                                          [(tx + sx * 16) * 2 + kw];
                            unsigned long long xx;
                            asm("mov.b64 %0, {%1, %1};" : "=l"(xx)
                                : "r"(__float_as_uint(xv)));
                            unsigned long long* a = &acc2[(sy * 2 + sx) * 8];
                            FMA_F32X2(a[0], xx, w0);
                            FMA_F32X2(a[1], xx, w1);
                            FMA_F32X2(a[2], xx, w2);
                            FMA_F32X2(a[3], xx, w3);
                            FMA_F32X2(a[4], xx, w4);
                            FMA_F32X2(a[5], xx, w5);
                            FMA_F32X2(a[6], xx, w6);
                            FMA_F32X2(a[7], xx, w7);
                        }
                    }
                }
            }
        }
        __syncthreads();
    }

    // epilogue: +agg_b, store
    float bv[OBLK];
    #pragma unroll
    for (int o = 0; o < OBLK; o++) bv[o] = g_aggb[b * DIM + og * OBLK + o];

    const size_t outbase = ((size_t)b * DIM + og * OBLK) * HWOUT;
    #pragma unroll
    for (int sy = 0; sy < 2; sy++) {
        #pragma unroll
        for (int sx = 0; sx < 2; sx++) {
            int ho = ho0 + ty + sy * 8;
            int wo = wo0 + tx + sx * 16;
            if (ho < HOUT && wo < HOUT) {
                float* ob = out + outbase + (size_t)ho * HOUT + wo;
                unsigned long long* a = &acc2[(sy * 2 + sx) * 8];
                #pragma unroll
                for (int j = 0; j < 8; j++) {
                    unsigned int lo, hi;
                    asm("mov.b64 {%0, %1}, %2;" : "=r"(lo), "=r"(hi) : "l"(a[j]));
                    ob[(size_t)(2 * j + 0) * HWOUT] = __uint_as_float(lo) + bv[2 * j + 0];
                    ob[(size_t)(2 * j + 1) * HWOUT] = __uint_as_float(hi) + bv[2 * j + 1];
                }
            }
        }
    }
}

// ---------------- launch ----------------
extern "C" void kernel_launch(void* const* d_in, const int* in_sizes, int n_in,
                              void* d_out, int out_size) {
    const float* x      = (const float*)d_in[0];
    const float* fc1_w  = (const float*)d_in[1];
    const float* fc1_b  = (const float*)d_in[2];
    const float* fc2_w  = (const float*)d_in[3];
    const float* fc2_b  = (const float*)d_in[4];
    const float* weight = (const float*)d_in[5];
    const float* bias   = (const float*)d_in[6];
    float* out = (float*)d_out;

    const size_t WRET_ELEMS = (size_t)BATCH * DIM * KS * KS * DIM;  // 1,638,400
    float* wret = out + ((size_t)out_size - WRET_ELEMS);

    pool_kernel<<<BATCH * DIM, 256>>>(x);
    att_kernel<<<1, 256>>>(fc1_w, fc1_b, fc2_w, fc2_b, bias);
    aggw_kernel<<<dim3(100, BATCH), 256>>>(weight, wret);
    conv_kernel<<<dim3(32, DIM / OBLK, BATCH), 128>>>(x, out);
}

// round 6
// speedup vs baseline: 2.4351x; 2.4351x over previous
#include <cuda_runtime.h>
#include <cuda_bf16.h>
#include <cstdint>

// ---------------- problem constants ----------------
#define BATCH 16
#define DIM   64
#define KNUM  4
#define HW    256
#define KS    5
#define HOUT  127          // (256 + 2 - 5)/2 + 1
#define HWOUT (HOUT*HOUT)  // 16129

// ---------------- device scratch (no allocs allowed) ----------------
__device__ float g_pooled[BATCH * DIM];
__device__ float g_att[BATCH * KNUM];
__device__ float g_aggb[BATCH * DIM];
// conv-friendly pre-split weights: [b][tap(25)][oc(64)][ic(64)], bf16 hi/lo
__device__ __nv_bfloat16 g_wb_hi[BATCH * 25 * DIM * DIM];
__device__ __nv_bfloat16 g_wb_lo[BATCH * 25 * DIM * DIM];

// ---------------- helpers ----------------
__device__ __forceinline__ uint32_t smem_u32(const void* p) {
    uint32_t a;
    asm("{ .reg .u64 t; cvta.to.shared.u64 t, %1; cvt.u32.u64 %0, t; }"
        : "=r"(a) : "l"(p));
    return a;
}

#define LDSM_X4(r0, r1, r2, r3, addr)                                        \
    asm volatile("ldmatrix.sync.aligned.m8n8.x4.shared.b16 {%0,%1,%2,%3}, [%4];" \
                 : "=r"(r0), "=r"(r1), "=r"(r2), "=r"(r3) : "r"(addr))

__device__ __forceinline__ void mma16816(float* c, const uint32_t* a,
                                         const uint32_t* bf) {
    asm volatile(
        "mma.sync.aligned.m16n8k16.row.col.f32.bf16.bf16.f32 "
        "{%0,%1,%2,%3}, {%4,%5,%6,%7}, {%8,%9}, {%0,%1,%2,%3};"
        : "+f"(c[0]), "+f"(c[1]), "+f"(c[2]), "+f"(c[3])
        : "r"(a[0]), "r"(a[1]), "r"(a[2]), "r"(a[3]), "r"(bf[0]), "r"(bf[1]));
}

// ---------------- kernel 1: global average pool ----------------
__global__ void pool_kernel(const float* __restrict__ x) {
    int bc = blockIdx.x;
    const float4* p = (const float4*)(x + (size_t)bc * (HW*HW));
    float s = 0.f;
    for (int i = threadIdx.x; i < (HW*HW)/4; i += 256) {
        float4 v = p[i];
        s += (v.x + v.y) + (v.z + v.w);
    }
    __shared__ float sm[256];
    sm[threadIdx.x] = s;
    __syncthreads();
    for (int off = 128; off > 0; off >>= 1) {
        if (threadIdx.x < off) sm[threadIdx.x] += sm[threadIdx.x + off];
        __syncthreads();
    }
    if (threadIdx.x == 0) g_pooled[bc] = sm[0] * (1.0f / (HW*HW));
}

// ---------------- kernel 2: attention + agg_b ----------------
__global__ void att_kernel(const float* __restrict__ fc1_w, const float* __restrict__ fc1_b,
                           const float* __restrict__ fc2_w, const float* __restrict__ fc2_b,
                           const float* __restrict__ bias) {
    __shared__ float att_s[BATCH][KNUM];
    int t = threadIdx.x;
    if (t < BATCH) {
        float a[KNUM];
        #pragma unroll
        for (int k = 0; k < KNUM; k++) {
            float s = fc1_b[k];
            for (int c = 0; c < DIM; c++) s += g_pooled[t * DIM + c] * fc1_w[k * DIM + c];
            a[k] = s > 0.f ? s : 0.f;
        }
        float l[KNUM], mx = -1e30f;
        #pragma unroll
        for (int k = 0; k < KNUM; k++) {
            float s = fc2_b[k];
            #pragma unroll
            for (int j = 0; j < KNUM; j++) s += a[j] * fc2_w[k * KNUM + j];
            l[k] = s;
            mx = fmaxf(mx, s);
        }
        float den = 0.f;
        #pragma unroll
        for (int k = 0; k < KNUM; k++) { l[k] = __expf(l[k] - mx); den += l[k]; }
        float inv = 1.0f / den;
        #pragma unroll
        for (int k = 0; k < KNUM; k++) {
            float v = l[k] * inv;
            att_s[t][k] = v;
            g_att[t * KNUM + k] = v;
        }
    }
    __syncthreads();
    for (int idx = t; idx < BATCH * DIM; idx += blockDim.x) {
        int b = idx / DIM, o = idx % DIM;
        float s = 0.f;
        #pragma unroll
        for (int k = 0; k < KNUM; k++) s += att_s[b][k] * bias[k * DIM + o];
        g_aggb[idx] = s;
    }
}

// ---------------- kernel 3: agg_w mix + w_ret + bf16 hi/lo split ----------------
__global__ void aggw_kernel(const float* __restrict__ weight, float* __restrict__ wret) {
    const int PER_B = DIM * DIM * KS * KS;   // 102400
    int b = blockIdx.y;
    float a0 = g_att[b * 4 + 0], a1 = g_att[b * 4 + 1];
    float a2 = g_att[b * 4 + 2], a3 = g_att[b * 4 + 3];
    for (int j = blockIdx.x * blockDim.x + threadIdx.x; j < PER_B;
         j += gridDim.x * blockDim.x) {
        float v = a0 * weight[j]
                + a1 * weight[PER_B + j]
                + a2 * weight[2 * PER_B + j]
                + a3 * weight[3 * PER_B + j];
        int o = j / (DIM * KS * KS);
        int r = j % (DIM * KS * KS);
        int i = r / (KS * KS);
        int p = r % (KS * KS);
        wret[(((size_t)b * DIM + o) * (KS * KS) + p) * DIM + i] = v;
        __nv_bfloat16 hi = __float2bfloat16(v);
        __nv_bfloat16 lo = __float2bfloat16(v - __bfloat162float(hi));
        size_t wb = ((size_t)(b * 25 + p) * DIM + o) * DIM + i;
        g_wb_hi[wb] = hi;
        g_wb_lo[wb] = lo;
    }
}

// ---------------- kernel 4: mma.sync implicit-GEMM conv ----------------
// CTA = (ho, b). D[128 pixels, 64 oc], K = 25 taps x 64 ic, bf16 3-term split.
// 8 warps: warp_m = wid&3 (m32), warp_n = wid>>2 (n32).
// SMEM (dynamic, bytes):
#define RAW_PITCH 260                        // floats per raw row (1040B)
#define RAW_OFF   0                          // 32*260*4 = 33280
#define A_PITCH   80                         // bytes per A/B row (32 bf16 = 64B + pad)
#define A_HI_OFF  33280                      // 128*80 = 10240
#define A_LO_OFF  43520
#define B_HI_OFF  53760                      // 64*80 = 5120
#define B_LO_OFF  58880
#define CONV_SMEM 64000

__global__ __launch_bounds__(256) void conv_mma_kernel(const float* __restrict__ x,
                                                       float* __restrict__ out) {
    extern __shared__ char smem[];
    const uint32_t sbase = smem_u32(smem);
    const int b  = blockIdx.y;
    const int ho = blockIdx.x;
    const int t  = threadIdx.x;
    const int wid = t >> 5;
    const int l   = t & 31;

    const int warp_m = wid & 3;           // 0..3
    const int warp_n = wid >> 2;          // 0..1
    const int mbase = warp_m * 32;
    const int nbase = warp_n * 32;

    float acc[2][4][4];
    #pragma unroll
    for (int f = 0; f < 2; f++)
        #pragma unroll
        for (int nf = 0; nf < 4; nf++)
            #pragma unroll
            for (int q = 0; q < 4; q++) acc[f][nf][q] = 0.f;

    float* raw = (float*)(smem + RAW_OFF);
    const float* xb = x + (size_t)b * DIM * (HW * HW);

    // per-lane ldmatrix address components
    const uint32_t frag_off = (uint32_t)(l & 15) * A_PITCH + (uint32_t)(l >> 4) * 16;
    const uint32_t aHi0 = sbase + A_HI_OFF + (uint32_t)mbase * A_PITCH + frag_off;
    const uint32_t aLo0 = sbase + A_LO_OFF + (uint32_t)mbase * A_PITCH + frag_off;
    const uint32_t bHi0 = sbase + B_HI_OFF + (uint32_t)nbase * A_PITCH + frag_off;
    const uint32_t bLo0 = sbase + B_LO_OFF + (uint32_t)nbase * A_PITCH + frag_off;

    const int pix  = t >> 1;              // 0..127 (A row)
    const int half = (t & 1) << 4;        // ic half 0/16

    for (int kh = 0; kh < KS; kh++) {
        int row = 2 * ho - 1 + kh;
        if (row < 0) continue;            // only ho=0, kh=0
        for (int ic0 = 0; ic0 < DIM; ic0 += 32) {
            // stage raw x row: 32 ic x 256 cols
            for (int idx = t; idx < 32 * 64; idx += 256) {
                int ic = idx >> 6;
                int c4 = (idx & 63) << 2;
                float4 v = *(const float4*)(xb + (size_t)(ic0 + ic) * (HW * HW)
                                            + (size_t)row * HW + c4);
                *(float4*)(raw + ic * RAW_PITCH + c4) = v;
            }
            __syncthreads();

            for (int kw = 0; kw < KS; kw++) {
                // ---- pack A[128][32] hi/lo bf16, pitch 80B ----
                {
                    int col = 2 * pix - 1 + kw;
                    bool ok = (col >= 0) && (col < HW);
                    const float* rp = raw + col;
                    char* arow_hi = smem + A_HI_OFF + pix * A_PITCH + half * 2;
                    char* arow_lo = smem + A_LO_OFF + pix * A_PITCH + half * 2;
                    #pragma unroll
                    for (int j = 0; j < 16; j += 2) {
                        int ic = half + j;
                        float v0 = ok ? rp[ic * RAW_PITCH] : 0.f;
                        float v1 = ok ? rp[(ic + 1) * RAW_PITCH] : 0.f;
                        __nv_bfloat162 h = __floats2bfloat162_rn(v0, v1);
                        float r0 = v0 - __bfloat162float(h.x);
                        float r1 = v1 - __bfloat162float(h.y);
                        __nv_bfloat162 l2 = __floats2bfloat162_rn(r0, r1);
                        *(__nv_bfloat162*)(arow_hi + j * 2) = h;
                        *(__nv_bfloat162*)(arow_lo + j * 2) = l2;
                    }
                }
                // ---- pack B[64][32] hi/lo (16B chunks from pre-split weights) ----
                {
                    int p = kh * KS + kw;
                    size_t base = (size_t)(b * 25 + p) * (DIM * DIM) + ic0;
                    #pragma unroll
                    for (int it = 0; it < 2; it++) {
                        int idx = t + it * 256;          // 0..511
                        int isl = idx >> 8;              // 0=hi, 1=lo
                        int r2  = idx & 255;
                        int oc  = r2 >> 2;
                        int q   = r2 & 3;
                        const __nv_bfloat16* src =
                            (isl ? g_wb_lo : g_wb_hi) + base + (size_t)oc * DIM + q * 8;
                        uint4 v = *(const uint4*)src;
                        *(uint4*)(smem + (isl ? B_LO_OFF : B_HI_OFF)
                                  + oc * A_PITCH + q * 16) = v;
                    }
                }
                __syncthreads();

                // ---- 2 k-steps of 16; 24 mma each ----
                #pragma unroll
                for (int s = 0; s < 2; s++) {
                    uint32_t ah[2][4], al[2][4], bh[4][2], bl[4][2];
                    #pragma unroll
                    for (int f = 0; f < 2; f++) {
                        LDSM_X4(ah[f][0], ah[f][1], ah[f][2], ah[f][3],
                                aHi0 + (uint32_t)f * (16 * A_PITCH) + s * 32);
                        LDSM_X4(al[f][0], al[f][1], al[f][2], al[f][3],
                                aLo0 + (uint32_t)f * (16 * A_PITCH) + s * 32);
                    }
                    #pragma unroll
                    for (int nb = 0; nb < 2; nb++) {
                        uint32_t r0, r1, r2, r3;
                        LDSM_X4(r0, r1, r2, r3,
                                bHi0 + (uint32_t)nb * (16 * A_PITCH) + s * 32);
                        bh[nb * 2][0] = r0; bh[nb * 2][1] = r2;
                        bh[nb * 2 + 1][0] = r1; bh[nb * 2 + 1][1] = r3;
                        LDSM_X4(r0, r1, r2, r3,
                                bLo0 + (uint32_t)nb * (16 * A_PITCH) + s * 32);
                        bl[nb * 2][0] = r0; bl[nb * 2][1] = r2;
                        bl[nb * 2 + 1][0] = r1; bl[nb * 2 + 1][1] = r3;
                    }
                    #pragma unroll
                    for (int f = 0; f < 2; f++)
                        #pragma unroll
                        for (int nf = 0; nf < 4; nf++) {
                            mma16816(acc[f][nf], ah[f], bh[nf]);
                            mma16816(acc[f][nf], ah[f], bl[nf]);
                            mma16816(acc[f][nf], al[f], bh[nf]);
                        }
                }
                __syncthreads();
            }
        }
    }

    // ---- epilogue: +bias, store ----
    float* bias_s = raw;                   // raw area free now
    if (t < DIM) bias_s[t] = g_aggb[b * DIM + t];
    __syncthreads();

    const size_t obase = (size_t)b * DIM * HWOUT + (size_t)ho * HOUT;
    const int wo_l = l >> 2;
    const int oc_l = 2 * (l & 3);
    #pragma unroll
    for (int f = 0; f < 2; f++) {
        int w1 = mbase + f * 16 + wo_l;
        int w2 = w1 + 8;
        #pragma unroll
        for (int nf = 0; nf < 4; nf++) {
            int oc = nbase + nf * 8 + oc_l;
            float b0 = bias_s[oc], b1 = bias_s[oc + 1];
            const float* c = acc[f][nf];
            if (w1 < HOUT) {
                out[obase + (size_t)oc * HWOUT + w1]       = c[0] + b0;
                out[obase + (size_t)(oc + 1) * HWOUT + w1] = c[1] + b1;
            }
            if (w2 < HOUT) {
                out[obase + (size_t)oc * HWOUT + w2]       = c[2] + b0;
                out[obase + (size_t)(oc + 1) * HWOUT + w2] = c[3] + b1;
            }
        }
    }
}

// ---------------- launch ----------------
extern "C" void kernel_launch(void* const* d_in, const int* in_sizes, int n_in,
                              void* d_out, int out_size) {
    const float* x      = (const float*)d_in[0];
    const float* fc1_w  = (const float*)d_in[1];
    const float* fc1_b  = (const float*)d_in[2];
    const float* fc2_w  = (const float*)d_in[3];
    const float* fc2_b  = (const float*)d_in[4];
    const float* weight = (const float*)d_in[5];
    const float* bias   = (const float*)d_in[6];
    float* out = (float*)d_out;

    const size_t WRET_ELEMS = (size_t)BATCH * DIM * KS * KS * DIM;  // 1,638,400
    float* wret = out + ((size_t)out_size - WRET_ELEMS);

    static int smem_set = 0;
    if (!smem_set) {
        cudaFuncSetAttribute(conv_mma_kernel,
                             cudaFuncAttributeMaxDynamicSharedMemorySize, CONV_SMEM);
        smem_set = 1;
    }

    pool_kernel<<<BATCH * DIM, 256>>>(x);
    att_kernel<<<1, 256>>>(fc1_w, fc1_b, fc2_w, fc2_b, bias);
    aggw_kernel<<<dim3(100, BATCH), 256>>>(weight, wret);
    conv_mma_kernel<<<dim3(HOUT, BATCH), 256, CONV_SMEM>>>(x, out);
}

// round 7
// speedup vs baseline: 2.8312x; 1.1626x over previous
#include <cuda_runtime.h>
#include <cuda_bf16.h>
#include <cstdint>

// ---------------- problem constants ----------------
#define BATCH 16
#define DIM   64
#define KNUM  4
#define HW    256
#define KS    5
#define HOUT  127          // (256 + 2 - 5)/2 + 1
#define HWOUT (HOUT*HOUT)  // 16129

// ---------------- device scratch (no allocs allowed) ----------------
__device__ float g_pooled[BATCH * DIM];
__device__ float g_att[BATCH * KNUM];
__device__ float g_aggb[BATCH * DIM];
// conv-friendly pre-split weights: [b][tap(25)][oc(64)][ic(64)], bf16 hi/lo
__device__ __nv_bfloat16 g_wb_hi[BATCH * 25 * DIM * DIM];
__device__ __nv_bfloat16 g_wb_lo[BATCH * 25 * DIM * DIM];

// ---------------- helpers ----------------
__device__ __forceinline__ uint32_t smem_u32(const void* p) {
    uint32_t a;
    asm("{ .reg .u64 t; cvta.to.shared.u64 t, %1; cvt.u32.u64 %0, t; }"
        : "=r"(a) : "l"(p));
    return a;
}

#define LDSM_X4(r0, r1, r2, r3, addr)                                        \
    asm volatile("ldmatrix.sync.aligned.m8n8.x4.shared.b16 {%0,%1,%2,%3}, [%4];" \
                 : "=r"(r0), "=r"(r1), "=r"(r2), "=r"(r3) : "r"(addr))

__device__ __forceinline__ void mma16816(float* c, const uint32_t* a,
                                         const uint32_t* bf) {
    asm volatile(
        "mma.sync.aligned.m16n8k16.row.col.f32.bf16.bf16.f32 "
        "{%0,%1,%2,%3}, {%4,%5,%6,%7}, {%8,%9}, {%0,%1,%2,%3};"
        : "+f"(c[0]), "+f"(c[1]), "+f"(c[2]), "+f"(c[3])
        : "r"(a[0]), "r"(a[1]), "r"(a[2]), "r"(a[3]), "r"(bf[0]), "r"(bf[1]));
}

// ---------------- kernel 1: global average pool ----------------
__global__ void pool_kernel(const float* __restrict__ x) {
    int bc = blockIdx.x;
    const float4* p = (const float4*)(x + (size_t)bc * (HW*HW));
    float s = 0.f;
    for (int i = threadIdx.x; i < (HW*HW)/4; i += 256) {
        float4 v = p[i];
        s += (v.x + v.y) + (v.z + v.w);
    }
    __shared__ float sm[256];
    sm[threadIdx.x] = s;
    __syncthreads();
    for (int off = 128; off > 0; off >>= 1) {
        if (threadIdx.x < off) sm[threadIdx.x] += sm[threadIdx.x + off];
        __syncthreads();
    }
    if (threadIdx.x == 0) g_pooled[bc] = sm[0] * (1.0f / (HW*HW));
}

// ---------------- kernel 2: attention + agg_b ----------------
__global__ void att_kernel(const float* __restrict__ fc1_w, const float* __restrict__ fc1_b,
                           const float* __restrict__ fc2_w, const float* __restrict__ fc2_b,
                           const float* __restrict__ bias) {
    __shared__ float att_s[BATCH][KNUM];
    int t = threadIdx.x;
    if (t < BATCH) {
        float a[KNUM];
        #pragma unroll
        for (int k = 0; k < KNUM; k++) {
            float s = fc1_b[k];
            for (int c = 0; c < DIM; c++) s += g_pooled[t * DIM + c] * fc1_w[k * DIM + c];
            a[k] = s > 0.f ? s : 0.f;
        }
        float l[KNUM], mx = -1e30f;
        #pragma unroll
        for (int k = 0; k < KNUM; k++) {
            float s = fc2_b[k];
            #pragma unroll
            for (int j = 0; j < KNUM; j++) s += a[j] * fc2_w[k * KNUM + j];
            l[k] = s;
            mx = fmaxf(mx, s);
        }
        float den = 0.f;
        #pragma unroll
        for (int k = 0; k < KNUM; k++) { l[k] = __expf(l[k] - mx); den += l[k]; }
        float inv = 1.0f / den;
        #pragma unroll
        for (int k = 0; k < KNUM; k++) {
            float v = l[k] * inv;
            att_s[t][k] = v;
            g_att[t * KNUM + k] = v;
        }
    }
    __syncthreads();
    for (int idx = t; idx < BATCH * DIM; idx += blockDim.x) {
        int b = idx / DIM, o = idx % DIM;
        float s = 0.f;
        #pragma unroll
        for (int k = 0; k < KNUM; k++) s += att_s[b][k] * bias[k * DIM + o];
        g_aggb[idx] = s;
    }
}

// ---------------- kernel 3: agg_w mix + w_ret + bf16 hi/lo split ----------------
__global__ void aggw_kernel(const float* __restrict__ weight, float* __restrict__ wret) {
    const int PER_B = DIM * DIM * KS * KS;   // 102400
    int b = blockIdx.y;
    float a0 = g_att[b * 4 + 0], a1 = g_att[b * 4 + 1];
    float a2 = g_att[b * 4 + 2], a3 = g_att[b * 4 + 3];
    for (int j = blockIdx.x * blockDim.x + threadIdx.x; j < PER_B;
         j += gridDim.x * blockDim.x) {
        float v = a0 * weight[j]
                + a1 * weight[PER_B + j]
                + a2 * weight[2 * PER_B + j]
                + a3 * weight[3 * PER_B + j];
        int o = j / (DIM * KS * KS);
        int r = j % (DIM * KS * KS);
        int i = r / (KS * KS);
        int p = r % (KS * KS);
        wret[(((size_t)b * DIM + o) * (KS * KS) + p) * DIM + i] = v;
        __nv_bfloat16 hi = __float2bfloat16(v);
        __nv_bfloat16 lo = __float2bfloat16(v - __bfloat162float(hi));
        size_t wb = ((size_t)(b * 25 + p) * DIM + o) * DIM + i;
        g_wb_hi[wb] = hi;
        g_wb_lo[wb] = lo;
    }
}

// ---------------- kernel 4: mma.sync implicit-GEMM conv (v2) ----------------
// CTA = (ho, b), 128 threads = 4 warps, each warp m32 x n64.
// A staged once per kh as bf16 hi/lo in even/odd column planes (pitch 144B,
// ldmatrix conflict-free); per-kw handled by per-lane ldmatrix addressing.
#define APITCH 144
#define PLANE  (130 * APITCH)       // 18720 B, rows 0 and 129 = zero guards
#define A_EH   0                    // even cols, hi
#define A_EL   18720                // even cols, lo   ( = A_EH + PLANE )
#define A_OH   37440                // odd  cols, hi
#define A_OL   56160                // odd  cols, lo
#define B_OFF  74880                // 2 bufs x (hi 9216 + lo 9216) = 36864
#define BIAS_OFF 111744
#define CONV_SMEM 112000

__global__ __launch_bounds__(128) void conv_mma_kernel(const float* __restrict__ x,
                                                       float* __restrict__ out) {
    extern __shared__ char smem[];
    const uint32_t sbase = smem_u32(smem);
    const int b  = blockIdx.y;
    const int ho = blockIdx.x;
    const int t  = threadIdx.x;
    const int wid = t >> 5;
    const int l   = t & 31;
    const int mbase = wid * 32;

    float acc[2][8][4];
    #pragma unroll
    for (int f = 0; f < 2; f++)
        #pragma unroll
        for (int nf = 0; nf < 8; nf++)
            #pragma unroll
            for (int q = 0; q < 4; q++) acc[f][nf][q] = 0.f;

    // zero guard rows (rows 0 and 129 of all 4 A planes) + stage bias
    for (int i = t; i < 288; i += 128) {           // 8 rows * 36 words
        int pl = i / 72;
        int r  = (i % 72) / 36;
        int w  = i % 36;
        *(uint32_t*)(smem + pl * PLANE + (r ? 129 : 0) * APITCH + w * 4) = 0;
    }
    if (t < DIM) ((float*)(smem + BIAS_OFF))[t] = g_aggb[b * DIM + t];

    const float* xb = x + (size_t)b * DIM * (HW * HW);

    // per-lane ldmatrix bases
    const uint32_t lrow = (uint32_t)(l & 15);
    const uint32_t lk16 = (uint32_t)(l >> 4) * 16;
    const uint32_t aRowOff = (uint32_t)(mbase + (int)lrow) * APITCH + lk16;
    const uint32_t bRowOff = lrow * APITCH + lk16;

    __syncthreads();

    for (int kh = 0; kh < KS; kh++) {
        int row = 2 * ho - 1 + kh;
        if (row < 0) continue;                 // only ho=0, kh=0
        __syncthreads();                       // prior tap readers done

        // ---- stage A planes: 64 ic x 256 cols -> bf16 hi/lo even/odd ----
        {
            const float* xrow = xb + (size_t)row * HW;
            for (int item = t; item < 1024; item += 128) {
                int icg = item >> 6;                   // 0..15 (ic = icg*4)
                int c4  = (item & 63) << 2;            // col base
                const float* p0 = xrow + (size_t)(icg * 4) * (HW * HW) + c4;
                float4 a0 = *(const float4*)(p0);
                float4 a1 = *(const float4*)(p0 + (HW * HW));
                float4 a2 = *(const float4*)(p0 + 2 * (HW * HW));
                float4 a3 = *(const float4*)(p0 + 3 * (HW * HW));
                float vs[4][4] = {{a0.x, a1.x, a2.x, a3.x},
                                  {a0.y, a1.y, a2.y, a3.y},
                                  {a0.z, a1.z, a2.z, a3.z},
                                  {a0.w, a1.w, a2.w, a3.w}};
                #pragma unroll
                for (int ci = 0; ci < 4; ci++) {
                    int col = c4 + ci;
                    float f0 = vs[ci][0], f1 = vs[ci][1];
                    float f2 = vs[ci][2], f3 = vs[ci][3];
                    __nv_bfloat162 h01 = __floats2bfloat162_rn(f0, f1);
                    __nv_bfloat162 h23 = __floats2bfloat162_rn(f2, f3);
                    __nv_bfloat162 l01 = __floats2bfloat162_rn(
                        f0 - __bfloat162float(h01.x), f1 - __bfloat162float(h01.y));
                    __nv_bfloat162 l23 = __floats2bfloat162_rn(
                        f2 - __bfloat162float(h23.x), f3 - __bfloat162float(h23.y));
                    char* plane = smem + ((col & 1) ? A_OH : A_EH);
                    uint32_t off = (uint32_t)((col >> 1) + 1) * APITCH + icg * 8;
                    uint2 hh, ll;
                    hh.x = *(uint32_t*)&h01; hh.y = *(uint32_t*)&h23;
                    ll.x = *(uint32_t*)&l01; ll.y = *(uint32_t*)&l23;
                    *(uint2*)(plane + off)         = hh;
                    *(uint2*)(plane + PLANE + off) = ll;   // lo plane
                }
            }
        }

        for (int kw = 0; kw < KS; kw++) {
            // ---- stage B[64 oc][64 ic] hi/lo into buf[kw&1] ----
            {
                int p = kh * KS + kw;
                size_t wbase = (size_t)(b * 25 + p) * (DIM * DIM);
                char* bbuf = smem + B_OFF + (kw & 1) * 18432;
                for (int it = t; it < 1024; it += 128) {
                    int isl = it >> 9;                 // 0=hi,1=lo
                    int r2  = it & 511;
                    int oc  = r2 >> 3;
                    int q   = r2 & 7;
                    const __nv_bfloat16* src =
                        (isl ? g_wb_lo : g_wb_hi) + wbase + (size_t)oc * DIM + q * 8;
                    uint4 v = *(const uint4*)src;
                    *(uint4*)(bbuf + isl * 9216 + oc * APITCH + q * 16) = v;
                }
            }
            __syncthreads();

            // ---- ldmatrix + mma: per-lane kw addressing, no A repack ----
            const int roff = (kw + 1) >> 1;                 // {0,1,1,2,2}
            const uint32_t aHiBase = sbase + ((kw & 1) ? A_EH : A_OH)
                                   + (uint32_t)roff * APITCH + aRowOff;
            const uint32_t bHiBase = sbase + B_OFF + (kw & 1) * 18432 + bRowOff;

            #pragma unroll
            for (int s = 0; s < 4; s++) {
                uint32_t ah[2][4], al[2][4];
                #pragma unroll
                for (int f = 0; f < 2; f++) {
                    uint32_t ra = aHiBase + (uint32_t)f * (16 * APITCH) + s * 32;
                    LDSM_X4(ah[f][0], ah[f][1], ah[f][2], ah[f][3], ra);
                    LDSM_X4(al[f][0], al[f][1], al[f][2], al[f][3], ra + PLANE);
                }
                #pragma unroll
                for (int nb = 0; nb < 4; nb++) {
                    uint32_t rb = bHiBase + (uint32_t)nb * (16 * APITCH) + s * 32;
                    uint32_t h0, h1, h2, h3;
                    LDSM_X4(h0, h1, h2, h3, rb);
                    uint32_t o0, o1, o2, o3;
                    LDSM_X4(o0, o1, o2, o3, rb + 9216);
                    uint32_t bh0[2] = {h0, h2}, bh1[2] = {h1, h3};
                    uint32_t bl0[2] = {o0, o2}, bl1[2] = {o1, o3};
                    #pragma unroll
                    for (int f = 0; f < 2; f++) {
                        mma16816(acc[f][nb * 2],     ah[f], bh0);
                        mma16816(acc[f][nb * 2],     ah[f], bl0);
                        mma16816(acc[f][nb * 2],     al[f], bh0);
                        mma16816(acc[f][nb * 2 + 1], ah[f], bh1);
                        mma16816(acc[f][nb * 2 + 1], ah[f], bl1);
                        mma16816(acc[f][nb * 2 + 1], al[f], bh1);
                    }
                }
            }
        }
    }

    // ---- epilogue: +bias, store ----
    __syncthreads();
    const float* bias_s = (const float*)(smem + BIAS_OFF);
    const size_t obase = (size_t)b * DIM * HWOUT + (size_t)ho * HOUT;
    const int wo_l = l >> 2;
    const int oc_l = 2 * (l & 3);
    #pragma unroll
    for (int f = 0; f < 2; f++) {
        int w1 = mbase + f * 16 + wo_l;
        int w2 = w1 + 8;
        #pragma unroll
        for (int nf = 0; nf < 8; nf++) {
            int oc = nf * 8 + oc_l;
            float b0 = bias_s[oc], b1 = bias_s[oc + 1];
            const float* c = acc[f][nf];
            if (w1 < HOUT) {
                out[obase + (size_t)oc * HWOUT + w1]       = c[0] + b0;
                out[obase + (size_t)(oc + 1) * HWOUT + w1] = c[1] + b1;
            }
            if (w2 < HOUT) {
                out[obase + (size_t)oc * HWOUT + w2]       = c[2] + b0;
                out[obase + (size_t)(oc + 1) * HWOUT + w2] = c[3] + b1;
            }
        }
    }
}

// ---------------- launch ----------------
extern "C" void kernel_launch(void* const* d_in, const int* in_sizes, int n_in,
                              void* d_out, int out_size) {
    const float* x      = (const float*)d_in[0];
    const float* fc1_w  = (const float*)d_in[1];
    const float* fc1_b  = (const float*)d_in[2];
    const float* fc2_w  = (const float*)d_in[3];
    const float* fc2_b  = (const float*)d_in[4];
    const float* weight = (const float*)d_in[5];
    const float* bias   = (const float*)d_in[6];
    float* out = (float*)d_out;

    const size_t WRET_ELEMS = (size_t)BATCH * DIM * KS * KS * DIM;  // 1,638,400
    float* wret = out + ((size_t)out_size - WRET_ELEMS);

    cudaFuncSetAttribute(conv_mma_kernel,
                         cudaFuncAttributeMaxDynamicSharedMemorySize, CONV_SMEM);

    pool_kernel<<<BATCH * DIM, 256>>>(x);
    att_kernel<<<1, 256>>>(fc1_w, fc1_b, fc2_w, fc2_b, bias);
    aggw_kernel<<<dim3(100, BATCH), 256>>>(weight, wret);
    conv_mma_kernel<<<dim3(HOUT, BATCH), 128, CONV_SMEM>>>(x, out);
}

// round 8
// speedup vs baseline: 4.1133x; 1.4529x over previous
#include <cuda_runtime.h>
#include <cuda_bf16.h>
#include <cuda_fp16.h>
#include <cstdint>

// ---------------- problem constants ----------------
#define BATCH 16
#define DIM   64
#define KNUM  4
#define HW    256
#define KS    5
#define HOUT  127          // (256 + 2 - 5)/2 + 1
#define HWOUT (HOUT*HOUT)  // 16129

// ---------------- device scratch (no allocs allowed) ----------------
__device__ float g_pooled[BATCH * DIM];
__device__ float g_att[BATCH * KNUM];
__device__ float g_aggb[BATCH * DIM];
// conv-friendly weights: [b][tap(25)][oc(64)][ic(64)], single fp16
__device__ __half g_wb[BATCH * 25 * DIM * DIM];

// ---------------- helpers ----------------
__device__ __forceinline__ uint32_t smem_u32(const void* p) {
    uint32_t a;
    asm("{ .reg .u64 t; cvta.to.shared.u64 t, %1; cvt.u32.u64 %0, t; }"
        : "=r"(a) : "l"(p));
    return a;
}

#define LDSM_X4(r0, r1, r2, r3, addr)                                        \
    asm volatile("ldmatrix.sync.aligned.m8n8.x4.shared.b16 {%0,%1,%2,%3}, [%4];" \
                 : "=r"(r0), "=r"(r1), "=r"(r2), "=r"(r3) : "r"(addr))

__device__ __forceinline__ void mma16816(float* c, const uint32_t* a,
                                         const uint32_t* bf) {
    asm volatile(
        "mma.sync.aligned.m16n8k16.row.col.f32.f16.f16.f32 "
        "{%0,%1,%2,%3}, {%4,%5,%6,%7}, {%8,%9}, {%0,%1,%2,%3};"
        : "+f"(c[0]), "+f"(c[1]), "+f"(c[2]), "+f"(c[3])
        : "r"(a[0]), "r"(a[1]), "r"(a[2]), "r"(a[3]), "r"(bf[0]), "r"(bf[1]));
}

__device__ __forceinline__ void cp_async16(uint32_t dst, const void* src) {
    asm volatile("cp.async.ca.shared.global [%0], [%1], 16;"
                 :: "r"(dst), "l"(src));
}
#define CP_COMMIT() asm volatile("cp.async.commit_group;")
#define CP_WAIT0()  asm volatile("cp.async.wait_group 0;")

// ---------------- kernel 1: global average pool ----------------
__global__ void pool_kernel(const float* __restrict__ x) {
    int bc = blockIdx.x;
    const float4* p = (const float4*)(x + (size_t)bc * (HW*HW));
    float s = 0.f;
    for (int i = threadIdx.x; i < (HW*HW)/4; i += 256) {
        float4 v = p[i];
        s += (v.x + v.y) + (v.z + v.w);
    }
    __shared__ float sm[256];
    sm[threadIdx.x] = s;
    __syncthreads();
    for (int off = 128; off > 0; off >>= 1) {
        if (threadIdx.x < off) sm[threadIdx.x] += sm[threadIdx.x + off];
        __syncthreads();
    }
    if (threadIdx.x == 0) g_pooled[bc] = sm[0] * (1.0f / (HW*HW));
}

// ---------------- kernel 2: attention + agg_b ----------------
__global__ void att_kernel(const float* __restrict__ fc1_w, const float* __restrict__ fc1_b,
                           const float* __restrict__ fc2_w, const float* __restrict__ fc2_b,
                           const float* __restrict__ bias) {
    __shared__ float att_s[BATCH][KNUM];
    int t = threadIdx.x;
    if (t < BATCH) {
        float a[KNUM];
        #pragma unroll
        for (int k = 0; k < KNUM; k++) {
            float s = fc1_b[k];
            for (int c = 0; c < DIM; c++) s += g_pooled[t * DIM + c] * fc1_w[k * DIM + c];
            a[k] = s > 0.f ? s : 0.f;
        }
        float l[KNUM], mx = -1e30f;
        #pragma unroll
        for (int k = 0; k < KNUM; k++) {
            float s = fc2_b[k];
            #pragma unroll
            for (int j = 0; j < KNUM; j++) s += a[j] * fc2_w[k * KNUM + j];
            l[k] = s;
            mx = fmaxf(mx, s);
        }
        float den = 0.f;
        #pragma unroll
        for (int k = 0; k < KNUM; k++) { l[k] = __expf(l[k] - mx); den += l[k]; }
        float inv = 1.0f / den;
        #pragma unroll
        for (int k = 0; k < KNUM; k++) {
            float v = l[k] * inv;
            att_s[t][k] = v;
            g_att[t * KNUM + k] = v;
        }
    }
    __syncthreads();
    for (int idx = t; idx < BATCH * DIM; idx += blockDim.x) {
        int b = idx / DIM, o = idx % DIM;
        float s = 0.f;
        #pragma unroll
        for (int k = 0; k < KNUM; k++) s += att_s[b][k] * bias[k * DIM + o];
        g_aggb[idx] = s;
    }
}

// ---------------- kernel 3: agg_w mix + w_ret + fp16 weights ----------------
__global__ void aggw_kernel(const float* __restrict__ weight, float* __restrict__ wret) {
    const int PER_B = DIM * DIM * KS * KS;   // 102400
    int b = blockIdx.y;
    float a0 = g_att[b * 4 + 0], a1 = g_att[b * 4 + 1];
    float a2 = g_att[b * 4 + 2], a3 = g_att[b * 4 + 3];
    for (int j = blockIdx.x * blockDim.x + threadIdx.x; j < PER_B;
         j += gridDim.x * blockDim.x) {
        float v = a0 * weight[j]
                + a1 * weight[PER_B + j]
                + a2 * weight[2 * PER_B + j]
                + a3 * weight[3 * PER_B + j];
        int o = j / (DIM * KS * KS);
        int r = j % (DIM * KS * KS);
        int i = r / (KS * KS);
        int p = r % (KS * KS);
        wret[(((size_t)b * DIM + o) * (KS * KS) + p) * DIM + i] = v;
        g_wb[((size_t)(b * 25 + p) * DIM + o) * DIM + i] = __float2half(v);
    }
}

// ---------------- kernel 4: mma.sync implicit-GEMM conv (v3, fp16) ----------------
// CTA = (ho, b), 128 threads = 4 warps, each warp m32 x n64.
// A staged once per kh as fp16 hi/lo in even/odd column planes (pitch 144B,
// ldmatrix conflict-free). B single fp16, cp.async double-buffered pipeline.
#define APITCH 144
#define PLANE  (130 * APITCH)       // 18720 B, rows 0 and 129 = zero guards
#define A_EH   0                    // even cols, hi   (lo = +PLANE)
#define A_OH   (2 * PLANE)          // odd  cols, hi   (lo = +PLANE)
#define B_OFF  74880                // 2 bufs x 9216 = 18432
#define BIAS_OFF 93312
#define CONV_SMEM 93568

__global__ __launch_bounds__(128) void conv_mma_kernel(const float* __restrict__ x,
                                                       float* __restrict__ out) {
    extern __shared__ char smem[];
    const uint32_t sbase = smem_u32(smem);
    const int b  = blockIdx.y;
    const int ho = blockIdx.x;
    const int t  = threadIdx.x;
    const int wid = t >> 5;
    const int l   = t & 31;
    const int mbase = wid * 32;

    float acc[2][8][4];
    #pragma unroll
    for (int f = 0; f < 2; f++)
        #pragma unroll
        for (int nf = 0; nf < 8; nf++)
            #pragma unroll
            for (int q = 0; q < 4; q++) acc[f][nf][q] = 0.f;

    // zero guard rows (rows 0 and 129 of all 4 A planes) + stage bias
    for (int i = t; i < 288; i += 128) {           // 4 planes * 2 rows * 36 words
        int pl = i / 72;
        int r  = (i % 72) / 36;
        int w  = i % 36;
        *(uint32_t*)(smem + pl * PLANE + (r ? 129 : 0) * APITCH + w * 4) = 0;
    }
    if (t < DIM) ((float*)(smem + BIAS_OFF))[t] = g_aggb[b * DIM + t];

    const float* xb = x + (size_t)b * DIM * (HW * HW);
    const __half* wbb = g_wb + (size_t)(b * 25) * (DIM * DIM);

    // per-lane ldmatrix bases
    const uint32_t lrow = (uint32_t)(l & 15);
    const uint32_t lk16 = (uint32_t)(l >> 4) * 16;
    const uint32_t aRowOff = (uint32_t)(mbase + (int)lrow) * APITCH + lk16;
    const uint32_t bRowOff = lrow * APITCH + lk16;

    // per-thread cp.async chunk mapping (4 x 16B per thread per tap)
    const int oc0 = t >> 3;            // chunks t, t+128, ...: oc = chunk>>3
    const int q0  = t & 7;

    for (int kh = 0; kh < KS; kh++) {
        int row = 2 * ho - 1 + kh;
        if (row < 0) continue;                 // only ho=0, kh=0
        __syncthreads();                       // prior readers of A planes + B bufs done

        // ---- stage A planes: 64 ic x 256 cols -> fp16 hi/lo even/odd ----
        {
            const float* xrow = xb + (size_t)row * HW;
            for (int item = t; item < 1024; item += 128) {
                int icg = item >> 6;                   // 0..15 (ic = icg*4)
                int c4  = (item & 63) << 2;            // col base
                const float* p0 = xrow + (size_t)(icg * 4) * (HW * HW) + c4;
                float4 a0 = *(const float4*)(p0);
                float4 a1 = *(const float4*)(p0 + (HW * HW));
                float4 a2 = *(const float4*)(p0 + 2 * (HW * HW));
                float4 a3 = *(const float4*)(p0 + 3 * (HW * HW));
                float vs[4][4] = {{a0.x, a1.x, a2.x, a3.x},
                                  {a0.y, a1.y, a2.y, a3.y},
                                  {a0.z, a1.z, a2.z, a3.z},
                                  {a0.w, a1.w, a2.w, a3.w}};
                #pragma unroll
                for (int ci = 0; ci < 4; ci++) {
                    int col = c4 + ci;
                    float f0 = vs[ci][0], f1 = vs[ci][1];
                    float f2 = vs[ci][2], f3 = vs[ci][3];
                    __half2 h01 = __floats2half2_rn(f0, f1);
                    __half2 h23 = __floats2half2_rn(f2, f3);
                    __half2 l01 = __floats2half2_rn(f0 - __low2float(h01),
                                                    f1 - __high2float(h01));
                    __half2 l23 = __floats2half2_rn(f2 - __low2float(h23),
                                                    f3 - __high2float(h23));
                    char* plane = smem + ((col & 1) ? A_OH : A_EH);
                    uint32_t off = (uint32_t)((col >> 1) + 1) * APITCH + icg * 8;
                    uint2 hh, ll;
                    hh.x = *(uint32_t*)&h01; hh.y = *(uint32_t*)&h23;
                    ll.x = *(uint32_t*)&l01; ll.y = *(uint32_t*)&l23;
                    *(uint2*)(plane + off)         = hh;
                    *(uint2*)(plane + PLANE + off) = ll;   // lo plane
                }
            }
        }

        // prefetch B for first tap of this kh into buf0
        {
            const __half* src = wbb + (size_t)(kh * KS) * (DIM * DIM);
            uint32_t dbase = sbase + B_OFF;
            #pragma unroll
            for (int it = 0; it < 4; it++) {
                int oc = oc0 + it * 16;
                cp_async16(dbase + oc * APITCH + q0 * 16, src + oc * DIM + q0 * 8);
            }
            CP_COMMIT();
        }

        for (int kw = 0; kw < KS; kw++) {
            CP_WAIT0();
            __syncthreads();                   // B[kw] + (first iter) A visible

            // prefetch B[kw+1] into the other buffer (overlaps MMAs below)
            if (kw < KS - 1) {
                const __half* src = wbb + (size_t)(kh * KS + kw + 1) * (DIM * DIM);
                uint32_t dbase = sbase + B_OFF + ((kw + 1) & 1) * 9216;
                #pragma unroll
                for (int it = 0; it < 4; it++) {
                    int oc = oc0 + it * 16;
                    cp_async16(dbase + oc * APITCH + q0 * 16, src + oc * DIM + q0 * 8);
                }
                CP_COMMIT();
            }

            // ---- ldmatrix + mma: per-lane kw addressing, no A repack ----
            const int roff = (kw + 1) >> 1;                 // {0,1,1,2,2}
            const uint32_t aHiBase = sbase + ((kw & 1) ? A_EH : A_OH)
                                   + (uint32_t)roff * APITCH + aRowOff;
            const uint32_t bBase = sbase + B_OFF + (kw & 1) * 9216 + bRowOff;

            #pragma unroll
            for (int s = 0; s < 4; s++) {
                uint32_t ah[2][4], al[2][4];
                #pragma unroll
                for (int f = 0; f < 2; f++) {
                    uint32_t ra = aHiBase + (uint32_t)f * (16 * APITCH) + s * 32;
                    LDSM_X4(ah[f][0], ah[f][1], ah[f][2], ah[f][3], ra);
                    LDSM_X4(al[f][0], al[f][1], al[f][2], al[f][3], ra + PLANE);
                }
                #pragma unroll
                for (int nb = 0; nb < 4; nb++) {
                    uint32_t b0, b1, b2, b3;
                    LDSM_X4(b0, b1, b2, b3,
                            bBase + (uint32_t)nb * (16 * APITCH) + s * 32);
                    uint32_t bf0[2] = {b0, b2}, bf1[2] = {b1, b3};
                    #pragma unroll
                    for (int f = 0; f < 2; f++) {
                        mma16816(acc[f][nb * 2],     ah[f], bf0);
                        mma16816(acc[f][nb * 2],     al[f], bf0);
                        mma16816(acc[f][nb * 2 + 1], ah[f], bf1);
                        mma16816(acc[f][nb * 2 + 1], al[f], bf1);
                    }
                }
            }
        }
    }

    // ---- epilogue: +bias, store ----
    __syncthreads();
    const float* bias_s = (const float*)(smem + BIAS_OFF);
    const size_t obase = (size_t)b * DIM * HWOUT + (size_t)ho * HOUT;
    const int wo_l = l >> 2;
    const int oc_l = 2 * (l & 3);
    #pragma unroll
    for (int f = 0; f < 2; f++) {
        int w1 = mbase + f * 16 + wo_l;
        int w2 = w1 + 8;
        #pragma unroll
        for (int nf = 0; nf < 8; nf++) {
            int oc = nf * 8 + oc_l;
            float b0 = bias_s[oc], b1 = bias_s[oc + 1];
            const float* c = acc[f][nf];
            if (w1 < HOUT) {
                out[obase + (size_t)oc * HWOUT + w1]       = c[0] + b0;
                out[obase + (size_t)(oc + 1) * HWOUT + w1] = c[1] + b1;
            }
            if (w2 < HOUT) {
                out[obase + (size_t)oc * HWOUT + w2]       = c[2] + b0;
                out[obase + (size_t)(oc + 1) * HWOUT + w2] = c[3] + b1;
            }
        }
    }
}

// ---------------- launch ----------------
extern "C" void kernel_launch(void* const* d_in, const int* in_sizes, int n_in,
                              void* d_out, int out_size) {
    const float* x      = (const float*)d_in[0];
    const float* fc1_w  = (const float*)d_in[1];
    const float* fc1_b  = (const float*)d_in[2];
    const float* fc2_w  = (const float*)d_in[3];
    const float* fc2_b  = (const float*)d_in[4];
    const float* weight = (const float*)d_in[5];
    const float* bias   = (const float*)d_in[6];
    float* out = (float*)d_out;

    const size_t WRET_ELEMS = (size_t)BATCH * DIM * KS * KS * DIM;  // 1,638,400
    float* wret = out + ((size_t)out_size - WRET_ELEMS);

    cudaFuncSetAttribute(conv_mma_kernel,
                         cudaFuncAttributeMaxDynamicSharedMemorySize, CONV_SMEM);

    pool_kernel<<<BATCH * DIM, 256>>>(x);
    att_kernel<<<1, 256>>>(fc1_w, fc1_b, fc2_w, fc2_b, bias);
    aggw_kernel<<<dim3(100, BATCH), 256>>>(weight, wret);
    conv_mma_kernel<<<dim3(HOUT, BATCH), 128, CONV_SMEM>>>(x, out);
}

// round 9
// speedup vs baseline: 6.5474x; 1.5918x over previous
#include <cuda_runtime.h>
#include <cuda_bf16.h>
#include <cuda_fp16.h>
#include <cstdint>

// ---------------- problem constants ----------------
#define BATCH 16
#define DIM   64
#define KNUM  4
#define HW    256
#define KS    5
#define HOUT  127          // (256 + 2 - 5)/2 + 1
#define HWOUT (HOUT*HOUT)  // 16129

// ---------------- device scratch (no allocs allowed) ----------------
__device__ float g_pooled[BATCH * DIM];
__device__ float g_att[BATCH * KNUM];
__device__ float g_aggb[BATCH * DIM];
// conv-friendly weights: [b][tap(25)][oc(64)][ic(64)], single fp16
__device__ __half g_wb[BATCH * 25 * DIM * DIM];

// ---------------- helpers ----------------
__device__ __forceinline__ uint32_t smem_u32(const void* p) {
    uint32_t a;
    asm("{ .reg .u64 t; cvta.to.shared.u64 t, %1; cvt.u32.u64 %0, t; }"
        : "=r"(a) : "l"(p));
    return a;
}

#define LDSM_X4(r0, r1, r2, r3, addr)                                        \
    asm volatile("ldmatrix.sync.aligned.m8n8.x4.shared.b16 {%0,%1,%2,%3}, [%4];" \
                 : "=r"(r0), "=r"(r1), "=r"(r2), "=r"(r3) : "r"(addr))

__device__ __forceinline__ void mma16816(float* c, const uint32_t* a,
                                         const uint32_t* bf) {
    asm volatile(
        "mma.sync.aligned.m16n8k16.row.col.f32.f16.f16.f32 "
        "{%0,%1,%2,%3}, {%4,%5,%6,%7}, {%8,%9}, {%0,%1,%2,%3};"
        : "+f"(c[0]), "+f"(c[1]), "+f"(c[2]), "+f"(c[3])
        : "r"(a[0]), "r"(a[1]), "r"(a[2]), "r"(a[3]), "r"(bf[0]), "r"(bf[1]));
}

__device__ __forceinline__ void cp_async16(uint32_t dst, const void* src) {
    asm volatile("cp.async.ca.shared.global [%0], [%1], 16;"
                 :: "r"(dst), "l"(src));
}
#define CP_COMMIT() asm volatile("cp.async.commit_group;")
#define CP_WAIT0()  asm volatile("cp.async.wait_group 0;")

// ---------------- kernel 1: global average pool ----------------
__global__ void pool_kernel(const float* __restrict__ x) {
    int bc = blockIdx.x;
    const float4* p = (const float4*)(x + (size_t)bc * (HW*HW));
    float s = 0.f;
    for (int i = threadIdx.x; i < (HW*HW)/4; i += 256) {
        float4 v = p[i];
        s += (v.x + v.y) + (v.z + v.w);
    }
    __shared__ float sm[256];
    sm[threadIdx.x] = s;
    __syncthreads();
    for (int off = 128; off > 0; off >>= 1) {
        if (threadIdx.x < off) sm[threadIdx.x] += sm[threadIdx.x + off];
        __syncthreads();
    }
    if (threadIdx.x == 0) g_pooled[bc] = sm[0] * (1.0f / (HW*HW));
}

// ---------------- kernel 2: attention + agg_b ----------------
__global__ void att_kernel(const float* __restrict__ fc1_w, const float* __restrict__ fc1_b,
                           const float* __restrict__ fc2_w, const float* __restrict__ fc2_b,
                           const float* __restrict__ bias) {
    __shared__ float att_s[BATCH][KNUM];
    int t = threadIdx.x;
    if (t < BATCH) {
        float a[KNUM];
        #pragma unroll
        for (int k = 0; k < KNUM; k++) {
            float s = fc1_b[k];
            for (int c = 0; c < DIM; c++) s += g_pooled[t * DIM + c] * fc1_w[k * DIM + c];
            a[k] = s > 0.f ? s : 0.f;
        }
        float l[KNUM], mx = -1e30f;
        #pragma unroll
        for (int k = 0; k < KNUM; k++) {
            float s = fc2_b[k];
            #pragma unroll
            for (int j = 0; j < KNUM; j++) s += a[j] * fc2_w[k * KNUM + j];
            l[k] = s;
            mx = fmaxf(mx, s);
        }
        float den = 0.f;
        #pragma unroll
        for (int k = 0; k < KNUM; k++) { l[k] = __expf(l[k] - mx); den += l[k]; }
        float inv = 1.0f / den;
        #pragma unroll
        for (int k = 0; k < KNUM; k++) {
            float v = l[k] * inv;
            att_s[t][k] = v;
            g_att[t * KNUM + k] = v;
        }
    }
    __syncthreads();
    for (int idx = t; idx < BATCH * DIM; idx += blockDim.x) {
        int b = idx / DIM, o = idx % DIM;
        float s = 0.f;
        #pragma unroll
        for (int k = 0; k < KNUM; k++) s += att_s[b][k] * bias[k * DIM + o];
        g_aggb[idx] = s;
    }
}

// ---------------- kernel 3: agg_w mix + w_ret + fp16 weights ----------------
__global__ void aggw_kernel(const float* __restrict__ weight, float* __restrict__ wret) {
    const int PER_B = DIM * DIM * KS * KS;   // 102400
    int b = blockIdx.y;
    float a0 = g_att[b * 4 + 0], a1 = g_att[b * 4 + 1];
    float a2 = g_att[b * 4 + 2], a3 = g_att[b * 4 + 3];
    for (int j = blockIdx.x * blockDim.x + threadIdx.x; j < PER_B;
         j += gridDim.x * blockDim.x) {
        float v = a0 * weight[j]
                + a1 * weight[PER_B + j]
                + a2 * weight[2 * PER_B + j]
                + a3 * weight[3 * PER_B + j];
        int o = j / (DIM * KS * KS);
        int r = j % (DIM * KS * KS);
        int i = r / (KS * KS);
        int p = r % (KS * KS);
        wret[(((size_t)b * DIM + o) * (KS * KS) + p) * DIM + i] = v;
        g_wb[((size_t)(b * 25 + p) * DIM + o) * DIM + i] = __float2half(v);
    }
}

// ---------------- kernel 4: mma.sync implicit-GEMM conv (v4, 1-term fp16) ----------------
// CTA = (ho, b), 128 threads = 4 warps, each warp m32 x n64.
// A staged once per kh as single fp16 in even/odd column planes (pitch 144B);
// per-kw handled by per-lane ldmatrix addressing. B fp16, cp.async double-buffer.
#define APITCH 144
#define PLANE  (130 * APITCH)       // 18720 B, rows 0 and 129 = zero guards
#define A_EH   0                    // even cols
#define A_OH   PLANE                // odd cols
#define B_OFF  37440                // 2 bufs x 9216 = 18432
#define BIAS_OFF 55872
#define CONV_SMEM 56128

__global__ __launch_bounds__(128, 4) void conv_mma_kernel(const float* __restrict__ x,
                                                          float* __restrict__ out) {
    extern __shared__ char smem[];
    const uint32_t sbase = smem_u32(smem);
    const int b  = blockIdx.y;
    const int ho = blockIdx.x;
    const int t  = threadIdx.x;
    const int wid = t >> 5;
    const int l   = t & 31;
    const int mbase = wid * 32;

    float acc[2][8][4];
    #pragma unroll
    for (int f = 0; f < 2; f++)
        #pragma unroll
        for (int nf = 0; nf < 8; nf++)
            #pragma unroll
            for (int q = 0; q < 4; q++) acc[f][nf][q] = 0.f;

    // zero guard rows (rows 0 and 129 of both A planes) + stage bias
    for (int i = t; i < 144; i += 128) {           // 2 planes * 2 rows * 36 words
        int pl = i / 72;
        int r  = (i % 72) / 36;
        int w  = i % 36;
        *(uint32_t*)(smem + pl * PLANE + (r ? 129 : 0) * APITCH + w * 4) = 0;
    }
    if (t < DIM) ((float*)(smem + BIAS_OFF))[t] = g_aggb[b * DIM + t];

    const float* xb = x + (size_t)b * DIM * (HW * HW);
    const __half* wbb = g_wb + (size_t)(b * 25) * (DIM * DIM);

    // per-lane ldmatrix bases
    const uint32_t lrow = (uint32_t)(l & 15);
    const uint32_t lk16 = (uint32_t)(l >> 4) * 16;
    const uint32_t aRowOff = (uint32_t)(mbase + (int)lrow) * APITCH + lk16;
    const uint32_t bRowOff = lrow * APITCH + lk16;

    // per-thread cp.async chunk mapping (4 x 16B per thread per tap)
    const int oc0 = t >> 3;
    const int q0  = t & 7;

    for (int kh = 0; kh < KS; kh++) {
        int row = 2 * ho - 1 + kh;
        if (row < 0) continue;                 // only ho=0, kh=0
        __syncthreads();                       // prior readers of A planes + B bufs done

        // ---- stage A planes: 64 ic x 256 cols -> single fp16 even/odd ----
        {
            const float* xrow = xb + (size_t)row * HW;
            for (int item = t; item < 1024; item += 128) {
                int icg = item >> 6;                   // 0..15 (ic = icg*4)
                int c4  = (item & 63) << 2;            // col base
                const float* p0 = xrow + (size_t)(icg * 4) * (HW * HW) + c4;
                float4 a0 = *(const float4*)(p0);
                float4 a1 = *(const float4*)(p0 + (HW * HW));
                float4 a2 = *(const float4*)(p0 + 2 * (HW * HW));
                float4 a3 = *(const float4*)(p0 + 3 * (HW * HW));
                float vs[4][4] = {{a0.x, a1.x, a2.x, a3.x},
                                  {a0.y, a1.y, a2.y, a3.y},
                                  {a0.z, a1.z, a2.z, a3.z},
                                  {a0.w, a1.w, a2.w, a3.w}};
                #pragma unroll
                for (int ci = 0; ci < 4; ci++) {
                    int col = c4 + ci;
                    __half2 h01 = __floats2half2_rn(vs[ci][0], vs[ci][1]);
                    __half2 h23 = __floats2half2_rn(vs[ci][2], vs[ci][3]);
                    char* plane = smem + ((col & 1) ? A_OH : A_EH);
                    uint32_t off = (uint32_t)((col >> 1) + 1) * APITCH + icg * 8;
                    uint2 hh;
                    hh.x = *(uint32_t*)&h01; hh.y = *(uint32_t*)&h23;
                    *(uint2*)(plane + off) = hh;
                }
            }
        }

        // prefetch B for first tap of this kh into buf0
        {
            const __half* src = wbb + (size_t)(kh * KS) * (DIM * DIM);
            uint32_t dbase = sbase + B_OFF;
            #pragma unroll
            for (int it = 0; it < 4; it++) {
                int oc = oc0 + it * 16;
                cp_async16(dbase + oc * APITCH + q0 * 16, src + oc * DIM + q0 * 8);
            }
            CP_COMMIT();
        }

        for (int kw = 0; kw < KS; kw++) {
            CP_WAIT0();
            __syncthreads();                   // B[kw] + (first iter) A visible

            // prefetch B[kw+1] into the other buffer (overlaps MMAs below)
            if (kw < KS - 1) {
                const __half* src = wbb + (size_t)(kh * KS + kw + 1) * (DIM * DIM);
                uint32_t dbase = sbase + B_OFF + ((kw + 1) & 1) * 9216;
                #pragma unroll
                for (int it = 0; it < 4; it++) {
                    int oc = oc0 + it * 16;
                    cp_async16(dbase + oc * APITCH + q0 * 16, src + oc * DIM + q0 * 8);
                }
                CP_COMMIT();
            }

            // ---- ldmatrix + mma ----
            const int roff = (kw + 1) >> 1;                 // {0,1,1,2,2}
            const uint32_t aBase = sbase + ((kw & 1) ? A_EH : A_OH)
                                 + (uint32_t)roff * APITCH + aRowOff;
            const uint32_t bBase = sbase + B_OFF + (kw & 1) * 9216 + bRowOff;

            #pragma unroll
            for (int s = 0; s < 4; s++) {
                uint32_t ah[2][4];
                #pragma unroll
                for (int f = 0; f < 2; f++) {
                    uint32_t ra = aBase + (uint32_t)f * (16 * APITCH) + s * 32;
                    LDSM_X4(ah[f][0], ah[f][1], ah[f][2], ah[f][3], ra);
                }
                #pragma unroll
                for (int nb = 0; nb < 4; nb++) {
                    uint32_t b0, b1, b2, b3;
                    LDSM_X4(b0, b1, b2, b3,
                            bBase + (uint32_t)nb * (16 * APITCH) + s * 32);
                    uint32_t bf0[2] = {b0, b2}, bf1[2] = {b1, b3};
                    #pragma unroll
                    for (int f = 0; f < 2; f++) {
                        mma16816(acc[f][nb * 2],     ah[f], bf0);
                        mma16816(acc[f][nb * 2 + 1], ah[f], bf1);
                    }
                }
            }
        }
    }

    // ---- epilogue: +bias, store ----
    __syncthreads();
    const float* bias_s = (const float*)(smem + BIAS_OFF);
    const size_t obase = (size_t)b * DIM * HWOUT + (size_t)ho * HOUT;
    const int wo_l = l >> 2;
    const int oc_l = 2 * (l & 3);
    #pragma unroll
    for (int f = 0; f < 2; f++) {
        int w1 = mbase + f * 16 + wo_l;
        int w2 = w1 + 8;
        #pragma unroll
        for (int nf = 0; nf < 8; nf++) {
            int oc = nf * 8 + oc_l;
            float b0 = bias_s[oc], b1 = bias_s[oc + 1];
            const float* c = acc[f][nf];
            if (w1 < HOUT) {
                out[obase + (size_t)oc * HWOUT + w1]       = c[0] + b0;
                out[obase + (size_t)(oc + 1) * HWOUT + w1] = c[1] + b1;
            }
            if (w2 < HOUT) {
                out[obase + (size_t)oc * HWOUT + w2]       = c[2] + b0;
                out[obase + (size_t)(oc + 1) * HWOUT + w2] = c[3] + b1;
            }
        }
    }
}

// ---------------- launch ----------------
extern "C" void kernel_launch(void* const* d_in, const int* in_sizes, int n_in,
                              void* d_out, int out_size) {
    const float* x      = (const float*)d_in[0];
    const float* fc1_w  = (const float*)d_in[1];
    const float* fc1_b  = (const float*)d_in[2];
    const float* fc2_w  = (const float*)d_in[3];
    const float* fc2_b  = (const float*)d_in[4];
    const float* weight = (const float*)d_in[5];
    const float* bias   = (const float*)d_in[6];
    float* out = (float*)d_out;

    const size_t WRET_ELEMS = (size_t)BATCH * DIM * KS * KS * DIM;  // 1,638,400
    float* wret = out + ((size_t)out_size - WRET_ELEMS);

    cudaFuncSetAttribute(conv_mma_kernel,
                         cudaFuncAttributeMaxDynamicSharedMemorySize, CONV_SMEM);

    pool_kernel<<<BATCH * DIM, 256>>>(x);
    att_kernel<<<1, 256>>>(fc1_w, fc1_b, fc2_w, fc2_b, bias);
    aggw_kernel<<<dim3(100, BATCH), 256>>>(weight, wret);
    conv_mma_kernel<<<dim3(HOUT, BATCH), 128, CONV_SMEM>>>(x, out);
}

// round 10
// speedup vs baseline: 7.0619x; 1.0786x over previous
#include <cuda_runtime.h>
#include <cuda_bf16.h>
#include <cuda_fp16.h>
#include <cstdint>

// ---------------- problem constants ----------------
#define BATCH 16
#define DIM   64
#define KNUM  4
#define HW    256
#define KS    5
#define HOUT  127          // (256 + 2 - 5)/2 + 1
#define HWOUT (HOUT*HOUT)  // 16129

// ---------------- device scratch (no allocs allowed) ----------------
__device__ float g_pooled[BATCH * DIM];              // SUMS (divide in att)
__device__ float g_att[BATCH * KNUM];
__device__ float g_aggb[BATCH * DIM];
// transposed fp16 input: [b][row][col][ic]  (134 MB)
__device__ __half g_xt[(size_t)BATCH * HW * HW * DIM];
// conv-friendly weights: [b][tap(25)][oc(64)][ic(64)], single fp16
__device__ __half g_wb[BATCH * 25 * DIM * DIM];

// ---------------- helpers ----------------
__device__ __forceinline__ uint32_t smem_u32(const void* p) {
    uint32_t a;
    asm("{ .reg .u64 t; cvta.to.shared.u64 t, %1; cvt.u32.u64 %0, t; }"
        : "=r"(a) : "l"(p));
    return a;
}

#define LDSM_X4(r0, r1, r2, r3, addr)                                        \
    asm volatile("ldmatrix.sync.aligned.m8n8.x4.shared.b16 {%0,%1,%2,%3}, [%4];" \
                 : "=r"(r0), "=r"(r1), "=r"(r2), "=r"(r3) : "r"(addr))

__device__ __forceinline__ void mma16816(float* c, const uint32_t* a,
                                         const uint32_t* bf) {
    asm volatile(
        "mma.sync.aligned.m16n8k16.row.col.f32.f16.f16.f32 "
        "{%0,%1,%2,%3}, {%4,%5,%6,%7}, {%8,%9}, {%0,%1,%2,%3};"
        : "+f"(c[0]), "+f"(c[1]), "+f"(c[2]), "+f"(c[3])
        : "r"(a[0]), "r"(a[1]), "r"(a[2]), "r"(a[3]), "r"(bf[0]), "r"(bf[1]));
}

__device__ __forceinline__ void cp_async16(uint32_t dst, const void* src) {
    asm volatile("cp.async.ca.shared.global [%0], [%1], 16;"
                 :: "r"(dst), "l"(src));
}
#define CP_COMMIT() asm volatile("cp.async.commit_group;")
#define CP_WAIT0()  asm volatile("cp.async.wait_group 0;")

// ---------------- kernel 0: zero the pooled sums ----------------
__global__ void zero_pool_kernel() {
    g_pooled[threadIdx.x] = 0.f;
}

// ---------------- kernel 1: transpose/convert x + pooled sums ----------------
// block = (row, b). Reads x[b][:, row, :] fp32, writes g_xt[b][row][:][:] fp16,
// accumulates per-ic row sums into g_pooled via atomicAdd.
__global__ __launch_bounds__(256) void transpose_pool_kernel(const float* __restrict__ x) {
    __shared__ uint32_t s[256][33];      // [col][ic_pair] half2
    __shared__ float psum[4][64];
    const int row = blockIdx.x;
    const int b   = blockIdx.y;
    const int t   = threadIdx.x;

    const float* xb = x + (size_t)b * DIM * (HW * HW) + (size_t)row * HW;
    #pragma unroll
    for (int k = 0; k < 8; k++) {
        int idx = t + 256 * k;                 // 0..2047
        int ic0 = idx >> 6;                    // 0..31  (ic pair)
        int c4  = (idx & 63) << 2;             // col base
        const float* p0 = xb + (size_t)(2 * ic0) * (HW * HW) + c4;
        float4 v0 = *(const float4*)p0;
        float4 v1 = *(const float4*)(p0 + (size_t)(HW * HW));
        __half2 h;
        h = __floats2half2_rn(v0.x, v1.x); s[c4 + 0][ic0] = *(uint32_t*)&h;
        h = __floats2half2_rn(v0.y, v1.y); s[c4 + 1][ic0] = *(uint32_t*)&h;
        h = __floats2half2_rn(v0.z, v1.z); s[c4 + 2][ic0] = *(uint32_t*)&h;
        h = __floats2half2_rn(v0.w, v1.w); s[c4 + 3][ic0] = *(uint32_t*)&h;
    }
    __syncthreads();

    // pooled partial sums (from fp16 — negligible error vs 1e-3 gate)
    {
        int ic = t & 63, part = t >> 6;
        float sum = 0.f;
        for (int c = part * 64; c < part * 64 + 64; c++) {
            uint32_t u = s[c][ic >> 1];
            __half2 h = *(__half2*)&u;
            sum += (ic & 1) ? __high2float(h) : __low2float(h);
        }
        psum[part][ic] = sum;
    }
    __syncthreads();
    if (t < 64)
        atomicAdd(&g_pooled[b * DIM + t],
                  psum[0][t] + psum[1][t] + psum[2][t] + psum[3][t]);

    // write transposed fp16: [col][ic] contiguous
    __half* dst = g_xt + (((size_t)b * HW + row) * HW) * DIM;
    #pragma unroll
    for (int o = 0; o < 8; o++) {
        int oi = t + 256 * o;                  // 0..2047
        int col = oi >> 3, q = oi & 7;
        uint2 w0, w1;
        w0.x = s[col][q * 4 + 0]; w0.y = s[col][q * 4 + 1];
        w1.x = s[col][q * 4 + 2]; w1.y = s[col][q * 4 + 3];
        *(uint2*)(dst + col * DIM + q * 8)     = w0;
        *(uint2*)(dst + col * DIM + q * 8 + 4) = w1;
    }
}

// ---------------- kernel 2: attention + agg_b ----------------
__global__ void att_kernel(const float* __restrict__ fc1_w, const float* __restrict__ fc1_b,
                           const float* __restrict__ fc2_w, const float* __restrict__ fc2_b,
                           const float* __restrict__ bias) {
    __shared__ float att_s[BATCH][KNUM];
    int t = threadIdx.x;
    if (t < BATCH) {
        const float inv_hw = 1.0f / (float)(HW * HW);
        float a[KNUM];
        #pragma unroll
        for (int k = 0; k < KNUM; k++) {
            float s = fc1_b[k];
            for (int c = 0; c < DIM; c++)
                s += (g_pooled[t * DIM + c] * inv_hw) * fc1_w[k * DIM + c];
            a[k] = s > 0.f ? s : 0.f;
        }
        float l[KNUM], mx = -1e30f;
        #pragma unroll
        for (int k = 0; k < KNUM; k++) {
            float s = fc2_b[k];
            #pragma unroll
            for (int j = 0; j < KNUM; j++) s += a[j] * fc2_w[k * KNUM + j];
            l[k] = s;
            mx = fmaxf(mx, s);
        }
        float den = 0.f;
        #pragma unroll
        for (int k = 0; k < KNUM; k++) { l[k] = __expf(l[k] - mx); den += l[k]; }
        float inv = 1.0f / den;
        #pragma unroll
        for (int k = 0; k < KNUM; k++) {
            float v = l[k] * inv;
            att_s[t][k] = v;
            g_att[t * KNUM + k] = v;
        }
    }
    __syncthreads();
    for (int idx = t; idx < BATCH * DIM; idx += blockDim.x) {
        int b = idx / DIM, o = idx % DIM;
        float s = 0.f;
        #pragma unroll
        for (int k = 0; k < KNUM; k++) s += att_s[b][k] * bias[k * DIM + o];
        g_aggb[idx] = s;
    }
}

// ---------------- kernel 3: agg_w mix + w_ret + fp16 weights ----------------
__global__ void aggw_kernel(const float* __restrict__ weight, float* __restrict__ wret) {
    const int PER_B = DIM * DIM * KS * KS;   // 102400
    int b = blockIdx.y;
    float a0 = g_att[b * 4 + 0], a1 = g_att[b * 4 + 1];
    float a2 = g_att[b * 4 + 2], a3 = g_att[b * 4 + 3];
    for (int j = blockIdx.x * blockDim.x + threadIdx.x; j < PER_B;
         j += gridDim.x * blockDim.x) {
        float v = a0 * weight[j]
                + a1 * weight[PER_B + j]
                + a2 * weight[2 * PER_B + j]
                + a3 * weight[3 * PER_B + j];
        int o = j / (DIM * KS * KS);
        int r = j % (DIM * KS * KS);
        int i = r / (KS * KS);
        int p = r % (KS * KS);
        wret[(((size_t)b * DIM + o) * (KS * KS) + p) * DIM + i] = v;
        g_wb[((size_t)(b * 25 + p) * DIM + o) * DIM + i] = __float2half(v);
    }
}

// ---------------- kernel 4: mma.sync implicit-GEMM conv (v5, async staging) ----------------
// CTA = (ho, b), 128 threads = 4 warps, each warp m32 x n64.
// A cp.async'd per kh from pre-transposed g_xt into even/odd pixel-column planes;
// B fp16 cp.async double-buffered. No in-kernel conversion.
#define APITCH 144
#define PLANE  (130 * APITCH)       // 18720 B, rows 0 and 129 = zero guards
#define A_EH   0                    // even cols
#define A_OH   PLANE                // odd cols
#define B_OFF  37440                // 2 bufs x 9216 = 18432
#define BIAS_OFF 55872
#define CONV_SMEM 56128

__global__ __launch_bounds__(128, 4) void conv_mma_kernel(float* __restrict__ out) {
    extern __shared__ char smem[];
    const uint32_t sbase = smem_u32(smem);
    const int b  = blockIdx.y;
    const int ho = blockIdx.x;
    const int t  = threadIdx.x;
    const int wid = t >> 5;
    const int l   = t & 31;
    const int mbase = wid * 32;

    float acc[2][8][4];
    #pragma unroll
    for (int f = 0; f < 2; f++)
        #pragma unroll
        for (int nf = 0; nf < 8; nf++)
            #pragma unroll
            for (int q = 0; q < 4; q++) acc[f][nf][q] = 0.f;

    // zero guard rows (rows 0 and 129 of both A planes) + stage bias
    for (int i = t; i < 144; i += 128) {           // 2 planes * 2 rows * 36 words
        int pl = i / 72;
        int r  = (i % 72) / 36;
        int w  = i % 36;
        *(uint32_t*)(smem + pl * PLANE + (r ? 129 : 0) * APITCH + w * 4) = 0;
    }
    if (t < DIM) ((float*)(smem + BIAS_OFF))[t] = g_aggb[b * DIM + t];

    const __half* wbb = g_wb + (size_t)(b * 25) * (DIM * DIM);

    // per-lane ldmatrix bases
    const uint32_t lrow = (uint32_t)(l & 15);
    const uint32_t lk16 = (uint32_t)(l >> 4) * 16;
    const uint32_t aRowOff = (uint32_t)(mbase + (int)lrow) * APITCH + lk16;
    const uint32_t bRowOff = lrow * APITCH + lk16;

    // per-thread cp.async chunk mapping for B (4 x 16B per tap)
    const int oc0 = t >> 3;
    const int q0  = t & 7;

    for (int kh = 0; kh < KS; kh++) {
        int row = 2 * ho - 1 + kh;
        if (row < 0) continue;                 // only ho=0, kh=0
        __syncthreads();                       // prior readers of A planes + B buf0 done

        // ---- A staging: 2048 x 16B cp.async from g_xt ----
        {
            const __half* xtr = g_xt + (((size_t)b * HW + row) * HW) * DIM;
            #pragma unroll
            for (int k = 0; k < 16; k++) {
                int c = t + 128 * k;               // 0..2047
                int col = c >> 3, q = c & 7;
                uint32_t dst = sbase + ((col & 1) ? A_OH : A_EH)
                             + (uint32_t)((col >> 1) + 1) * APITCH + q * 16;
                cp_async16(dst, xtr + col * DIM + q * 8);
            }
        }
        // ---- B first tap of this kh into buf0 (same group) ----
        {
            const __half* src = wbb + (size_t)(kh * KS) * (DIM * DIM);
            uint32_t dbase = sbase + B_OFF;
            #pragma unroll
            for (int it = 0; it < 4; it++) {
                int oc = oc0 + it * 16;
                cp_async16(dbase + oc * APITCH + q0 * 16, src + oc * DIM + q0 * 8);
            }
        }
        CP_COMMIT();

        for (int kw = 0; kw < KS; kw++) {
            CP_WAIT0();
            __syncthreads();                   // staged data visible to all warps

            // prefetch B[kw+1] into the other buffer (overlaps MMAs below)
            if (kw < KS - 1) {
                const __half* src = wbb + (size_t)(kh * KS + kw + 1) * (DIM * DIM);
                uint32_t dbase = sbase + B_OFF + ((kw + 1) & 1) * 9216;
                #pragma unroll
                for (int it = 0; it < 4; it++) {
                    int oc = oc0 + it * 16;
                    cp_async16(dbase + oc * APITCH + q0 * 16, src + oc * DIM + q0 * 8);
                }
                CP_COMMIT();
            }

            // ---- ldmatrix + mma ----
            const int roff = (kw + 1) >> 1;                 // {0,1,1,2,2}
            const uint32_t aBase = sbase + ((kw & 1) ? A_EH : A_OH)
                                 + (uint32_t)roff * APITCH + aRowOff;
            const uint32_t bBase = sbase + B_OFF + (kw & 1) * 9216 + bRowOff;

            #pragma unroll
            for (int s = 0; s < 4; s++) {
                uint32_t ah[2][4];
                #pragma unroll
                for (int f = 0; f < 2; f++) {
                    uint32_t ra = aBase + (uint32_t)f * (16 * APITCH) + s * 32;
                    LDSM_X4(ah[f][0], ah[f][1], ah[f][2], ah[f][3], ra);
                }
                #pragma unroll
                for (int nb = 0; nb < 4; nb++) {
                    uint32_t b0, b1, b2, b3;
                    LDSM_X4(b0, b1, b2, b3,
                            bBase + (uint32_t)nb * (16 * APITCH) + s * 32);
                    uint32_t bf0[2] = {b0, b2}, bf1[2] = {b1, b3};
                    #pragma unroll
                    for (int f = 0; f < 2; f++) {
                        mma16816(acc[f][nb * 2],     ah[f], bf0);
                        mma16816(acc[f][nb * 2 + 1], ah[f], bf1);
                    }
                }
            }
        }
    }

    // ---- epilogue: +bias, store ----
    __syncthreads();
    const float* bias_s = (const float*)(smem + BIAS_OFF);
    const size_t obase = (size_t)b * DIM * HWOUT + (size_t)ho * HOUT;
    const int wo_l = l >> 2;
    const int oc_l = 2 * (l & 3);
    #pragma unroll
    for (int f = 0; f < 2; f++) {
        int w1 = mbase + f * 16 + wo_l;
        int w2 = w1 + 8;
        #pragma unroll
        for (int nf = 0; nf < 8; nf++) {
            int oc = nf * 8 + oc_l;
            float b0 = bias_s[oc], b1 = bias_s[oc + 1];
            const float* c = acc[f][nf];
            if (w1 < HOUT) {
                out[obase + (size_t)oc * HWOUT + w1]       = c[0] + b0;
                out[obase + (size_t)(oc + 1) * HWOUT + w1] = c[1] + b1;
            }
            if (w2 < HOUT) {
                out[obase + (size_t)oc * HWOUT + w2]       = c[2] + b0;
                out[obase + (size_t)(oc + 1) * HWOUT + w2] = c[3] + b1;
            }
        }
    }
}

// ---------------- launch ----------------
extern "C" void kernel_launch(void* const* d_in, const int* in_sizes, int n_in,
                              void* d_out, int out_size) {
    const float* x      = (const float*)d_in[0];
    const float* fc1_w  = (const float*)d_in[1];
    const float* fc1_b  = (const float*)d_in[2];
    const float* fc2_w  = (const float*)d_in[3];
    const float* fc2_b  = (const float*)d_in[4];
    const float* weight = (const float*)d_in[5];
    const float* bias   = (const float*)d_in[6];
    float* out = (float*)d_out;

    const size_t WRET_ELEMS = (size_t)BATCH * DIM * KS * KS * DIM;  // 1,638,400
    float* wret = out + ((size_t)out_size - WRET_ELEMS);

    cudaFuncSetAttribute(conv_mma_kernel,
                         cudaFuncAttributeMaxDynamicSharedMemorySize, CONV_SMEM);

    zero_pool_kernel<<<1, BATCH * DIM>>>();
    transpose_pool_kernel<<<dim3(HW, BATCH), 256>>>(x);
    att_kernel<<<1, 256>>>(fc1_w, fc1_b, fc2_w, fc2_b, bias);
    aggw_kernel<<<dim3(100, BATCH), 256>>>(weight, wret);
    conv_mma_kernel<<<dim3(HOUT, BATCH), 128, CONV_SMEM>>>(out);
}

// round 12
// speedup vs baseline: 7.5933x; 1.0753x over previous
#include <cuda_runtime.h>
#include <cuda_bf16.h>
#include <cuda_fp16.h>
#include <cstdint>

// ---------------- problem constants ----------------
#define BATCH 16
#define DIM   64
#define KNUM  4
#define HW    256
#define KS    5
#define HOUT  127          // (256 + 2 - 5)/2 + 1
#define HWOUT (HOUT*HOUT)  // 16129

// ---------------- device scratch (no allocs allowed) ----------------
__device__ float g_pooled[BATCH * DIM];              // SUMS (divide in att)
__device__ float g_att[BATCH * KNUM];
__device__ float g_aggb[BATCH * DIM];
// transposed fp16 input: [b][row][col][ic]  (134 MB)
__device__ __half g_xt[(size_t)BATCH * HW * HW * DIM];
// conv-friendly weights: [b][tap(25)][oc(64)][ic(64)], single fp16
__device__ __half g_wb[BATCH * 25 * DIM * DIM];

// ---------------- helpers ----------------
__device__ __forceinline__ uint32_t smem_u32(const void* p) {
    uint32_t a;
    asm("{ .reg .u64 t; cvta.to.shared.u64 t, %1; cvt.u32.u64 %0, t; }"
        : "=r"(a) : "l"(p));
    return a;
}

#define LDSM_X4(r0, r1, r2, r3, addr)                                        \
    asm volatile("ldmatrix.sync.aligned.m8n8.x4.shared.b16 {%0,%1,%2,%3}, [%4];" \
                 : "=r"(r0), "=r"(r1), "=r"(r2), "=r"(r3) : "r"(addr))

__device__ __forceinline__ void mma16816(float* c, const uint32_t* a,
                                         const uint32_t* bf) {
    asm volatile(
        "mma.sync.aligned.m16n8k16.row.col.f32.f16.f16.f32 "
        "{%0,%1,%2,%3}, {%4,%5,%6,%7}, {%8,%9}, {%0,%1,%2,%3};"
        : "+f"(c[0]), "+f"(c[1]), "+f"(c[2]), "+f"(c[3])
        : "r"(a[0]), "r"(a[1]), "r"(a[2]), "r"(a[3]), "r"(bf[0]), "r"(bf[1]));
}

__device__ __forceinline__ void cp_async16(uint32_t dst, const void* src) {
    asm volatile("cp.async.ca.shared.global [%0], [%1], 16;"
                 :: "r"(dst), "l"(src));
}
#define CP_COMMIT() asm volatile("cp.async.commit_group;")
#define CP_WAIT0()  asm volatile("cp.async.wait_group 0;")

// ---------------- kernel 0: zero the pooled sums ----------------
__global__ void zero_pool_kernel() {
    g_pooled[threadIdx.x] = 0.f;
}

// ---------------- kernel 1: transpose/convert x + pooled sums ----------------
__global__ __launch_bounds__(256) void transpose_pool_kernel(const float* __restrict__ x) {
    __shared__ uint32_t s[256][33];      // [col][ic_pair] half2
    __shared__ float psum[4][64];
    const int row = blockIdx.x;
    const int b   = blockIdx.y;
    const int t   = threadIdx.x;

    const float* xb = x + (size_t)b * DIM * (HW * HW) + (size_t)row * HW;
    #pragma unroll
    for (int k = 0; k < 8; k++) {
        int idx = t + 256 * k;                 // 0..2047
        int ic0 = idx >> 6;                    // 0..31  (ic pair)
        int c4  = (idx & 63) << 2;             // col base
        const float* p0 = xb + (size_t)(2 * ic0) * (HW * HW) + c4;
        float4 v0 = *(const float4*)p0;
        float4 v1 = *(const float4*)(p0 + (size_t)(HW * HW));
        __half2 h;
        h = __floats2half2_rn(v0.x, v1.x); s[c4 + 0][ic0] = *(uint32_t*)&h;
        h = __floats2half2_rn(v0.y, v1.y); s[c4 + 1][ic0] = *(uint32_t*)&h;
        h = __floats2half2_rn(v0.z, v1.z); s[c4 + 2][ic0] = *(uint32_t*)&h;
        h = __floats2half2_rn(v0.w, v1.w); s[c4 + 3][ic0] = *(uint32_t*)&h;
    }
    __syncthreads();

    {
        int ic = t & 63, part = t >> 6;
        float sum = 0.f;
        for (int c = part * 64; c < part * 64 + 64; c++) {
            uint32_t u = s[c][ic >> 1];
            __half2 h = *(__half2*)&u;
            sum += (ic & 1) ? __high2float(h) : __low2float(h);
        }
        psum[part][ic] = sum;
    }
    __syncthreads();
    if (t < 64)
        atomicAdd(&g_pooled[b * DIM + t],
                  psum[0][t] + psum[1][t] + psum[2][t] + psum[3][t]);

    __half* dst = g_xt + (((size_t)b * HW + row) * HW) * DIM;
    #pragma unroll
    for (int o = 0; o < 8; o++) {
        int oi = t + 256 * o;                  // 0..2047
        int col = oi >> 3, q = oi & 7;
        uint2 w0, w1;
        w0.x = s[col][q * 4 + 0]; w0.y = s[col][q * 4 + 1];
        w1.x = s[col][q * 4 + 2]; w1.y = s[col][q * 4 + 3];
        *(uint2*)(dst + col * DIM + q * 8)     = w0;
        *(uint2*)(dst + col * DIM + q * 8 + 4) = w1;
    }
}

// ---------------- kernel 2: attention + agg_b ----------------
__global__ void att_kernel(const float* __restrict__ fc1_w, const float* __restrict__ fc1_b,
                           const float* __restrict__ fc2_w, const float* __restrict__ fc2_b,
                           const float* __restrict__ bias) {
    __shared__ float att_s[BATCH][KNUM];
    int t = threadIdx.x;
    if (t < BATCH) {
        const float inv_hw = 1.0f / (float)(HW * HW);
        float a[KNUM];
        #pragma unroll
        for (int k = 0; k < KNUM; k++) {
            float s = fc1_b[k];
            for (int c = 0; c < DIM; c++)
                s += (g_pooled[t * DIM + c] * inv_hw) * fc1_w[k * DIM + c];
            a[k] = s > 0.f ? s : 0.f;
        }
        float l[KNUM], mx = -1e30f;
        #pragma unroll
        for (int k = 0; k < KNUM; k++) {
            float s = fc2_b[k];
            #pragma unroll
            for (int j = 0; j < KNUM; j++) s += a[j] * fc2_w[k * KNUM + j];
            l[k] = s;
            mx = fmaxf(mx, s);
        }
        float den = 0.f;
        #pragma unroll
        for (int k = 0; k < KNUM; k++) { l[k] = __expf(l[k] - mx); den += l[k]; }
        float inv = 1.0f / den;
        #pragma unroll
        for (int k = 0; k < KNUM; k++) {
            float v = l[k] * inv;
            att_s[t][k] = v;
            g_att[t * KNUM + k] = v;
        }
    }
    __syncthreads();
    for (int idx = t; idx < BATCH * DIM; idx += blockDim.x) {
        int b = idx / DIM, o = idx % DIM;
        float s = 0.f;
        #pragma unroll
        for (int k = 0; k < KNUM; k++) s += att_s[b][k] * bias[k * DIM + o];
        g_aggb[idx] = s;
    }
}

// ---------------- kernel 3: agg_w mix + w_ret + fp16 weights (v2, coalesced) ----------------
// block = (oc, b). Reads the (k,o)-planes contiguously, transposes via smem,
// writes wret in 6.4KB contiguous runs and g_wb in 128B runs.
__global__ __launch_bounds__(256) void aggw_kernel(const float* __restrict__ weight,
                                                   float* __restrict__ wret) {
    __shared__ float v[DIM * KS * KS];       // 1600 floats, [i*25+p]
    const int PER_B = DIM * DIM * KS * KS;   // 102400
    const int o = blockIdx.x;
    const int b = blockIdx.y;
    const float a0 = g_att[b * 4 + 0], a1 = g_att[b * 4 + 1];
    const float a2 = g_att[b * 4 + 2], a3 = g_att[b * 4 + 3];

    const float* w0 = weight + (size_t)o * (DIM * KS * KS);
    for (int j = threadIdx.x; j < DIM * KS * KS; j += 256) {
        v[j] = a0 * w0[j]
             + a1 * w0[PER_B + j]
             + a2 * w0[2 * PER_B + j]
             + a3 * w0[3 * PER_B + j];
    }
    __syncthreads();

    float* wr = wret + ((size_t)(b * DIM + o)) * (KS * KS * DIM);
    for (int j = threadIdx.x; j < DIM * KS * KS; j += 256) {
        int p = j >> 6, i = j & 63;          // j = p*64 + i
        float val = v[i * (KS * KS) + p];
        wr[j] = val;                          // [p][i] contiguous
        g_wb[((size_t)(b * 25 + p) * DIM + o) * DIM + i] = __float2half(val);
    }
}

// ---------------- kernel 4: mma.sync implicit-GEMM conv (v6, paired s-steps) ----------------
#define APITCH 144
#define PLANE  (130 * APITCH)       // 18720 B, rows 0 and 129 = zero guards
#define A_EH   0                    // even cols
#define A_OH   PLANE                // odd cols
#define B_OFF  37440                // 2 bufs x 9216 = 18432
#define BIAS_OFF 55872
#define CONV_SMEM 56128

__global__ __launch_bounds__(128, 4) void conv_mma_kernel(float* __restrict__ out) {
    extern __shared__ char smem[];
    const uint32_t sbase = smem_u32(smem);
    const int b  = blockIdx.y;
    const int ho = blockIdx.x;
    const int t  = threadIdx.x;
    const int wid = t >> 5;
    const int l   = t & 31;
    const int mbase = wid * 32;

    float acc[2][8][4];
    #pragma unroll
    for (int f = 0; f < 2; f++)
        #pragma unroll
        for (int nf = 0; nf < 8; nf++)
            #pragma unroll
            for (int q = 0; q < 4; q++) acc[f][nf][q] = 0.f;

    for (int i = t; i < 144; i += 128) {           // zero guard rows
        int pl = i / 72;
        int r  = (i % 72) / 36;
        int w  = i % 36;
        *(uint32_t*)(smem + pl * PLANE + (r ? 129 : 0) * APITCH + w * 4) = 0;
    }
    if (t < DIM) ((float*)(smem + BIAS_OFF))[t] = g_aggb[b * DIM + t];

    const __half* wbb = g_wb + (size_t)(b * 25) * (DIM * DIM);

    const uint32_t lrow = (uint32_t)(l & 15);
    const uint32_t lk16 = (uint32_t)(l >> 4) * 16;
    const uint32_t aRowOff = (uint32_t)(mbase + (int)lrow) * APITCH + lk16;
    const uint32_t bRowOff = lrow * APITCH + lk16;

    const int oc0 = t >> 3;
    const int q0  = t & 7;

    for (int kh = 0; kh < KS; kh++) {
        int row = 2 * ho - 1 + kh;
        if (row < 0) continue;                 // only ho=0, kh=0
        __syncthreads();                       // prior readers of A planes + B buf0 done

        // ---- A staging: 2048 x 16B cp.async from g_xt ----
        {
            const __half* xtr = g_xt + (((size_t)b * HW + row) * HW) * DIM;
            #pragma unroll
            for (int k = 0; k < 16; k++) {
                int c = t + 128 * k;               // 0..2047
                int col = c >> 3, q = c & 7;
                uint32_t dst = sbase + ((col & 1) ? A_OH : A_EH)
                             + (uint32_t)((col >> 1) + 1) * APITCH + q * 16;
                cp_async16(dst, xtr + col * DIM + q * 8);
            }
        }
        // ---- B first tap of this kh into buf0 (same group) ----
        {
            const __half* src = wbb + (size_t)(kh * KS) * (DIM * DIM);
            uint32_t dbase = sbase + B_OFF;
            #pragma unroll
            for (int it = 0; it < 4; it++) {
                int oc = oc0 + it * 16;
                cp_async16(dbase + oc * APITCH + q0 * 16, src + oc * DIM + q0 * 8);
            }
        }
        CP_COMMIT();

        for (int kw = 0; kw < KS; kw++) {
            CP_WAIT0();
            __syncthreads();                   // staged data visible to all warps

            if (kw < KS - 1) {
                const __half* src = wbb + (size_t)(kh * KS + kw + 1) * (DIM * DIM);
                uint32_t dbase = sbase + B_OFF + ((kw + 1) & 1) * 9216;
                #pragma unroll
                for (int it = 0; it < 4; it++) {
                    int oc = oc0 + it * 16;
                    cp_async16(dbase + oc * APITCH + q0 * 16, src + oc * DIM + q0 * 8);
                }
                CP_COMMIT();
            }

            const int roff = (kw + 1) >> 1;                 // {0,1,1,2,2}
            const uint32_t aBase = sbase + ((kw & 1) ? A_EH : A_OH)
                                 + (uint32_t)roff * APITCH + aRowOff;
            const uint32_t bBase = sbase + B_OFF + (kw & 1) * 9216 + bRowOff;

            // ---- paired s-steps: batch 12 LDSM, then 32 MMAs ----
            #pragma unroll
            for (int sp = 0; sp < 2; sp++) {
                uint32_t ah[2][2][4];          // [s-in-pair][f]
                uint32_t bb[2][4][4];          // [s-in-pair][nb]
                #pragma unroll
                for (int sh = 0; sh < 2; sh++) {
                    const int s = sp * 2 + sh;
                    #pragma unroll
                    for (int f = 0; f < 2; f++) {
                        uint32_t ra = aBase + (uint32_t)f * (16 * APITCH) + s * 32;
                        LDSM_X4(ah[sh][f][0], ah[sh][f][1], ah[sh][f][2], ah[sh][f][3], ra);
                    }
                    #pragma unroll
                    for (int nb = 0; nb < 4; nb++) {
                        uint32_t rb = bBase + (uint32_t)nb * (16 * APITCH) + s * 32;
                        LDSM_X4(bb[sh][nb][0], bb[sh][nb][1], bb[sh][nb][2], bb[sh][nb][3], rb);
                    }
                }
                #pragma unroll
                for (int sh = 0; sh < 2; sh++)
                    #pragma unroll
                    for (int nb = 0; nb < 4; nb++) {
                        uint32_t bf0[2] = {bb[sh][nb][0], bb[sh][nb][2]};
                        uint32_t bf1[2] = {bb[sh][nb][1], bb[sh][nb][3]};
                        #pragma unroll
                        for (int f = 0; f < 2; f++) {
                            mma16816(acc[f][nb * 2],     ah[sh][f], bf0);
                            mma16816(acc[f][nb * 2 + 1], ah[sh][f], bf1);
                        }
                    }
            }
        }
    }

    // ---- epilogue: +bias, store ----
    __syncthreads();
    const float* bias_s = (const float*)(smem + BIAS_OFF);
    const size_t obase = (size_t)b * DIM * HWOUT + (size_t)ho * HOUT;
    const int wo_l = l >> 2;
    const int oc_l = 2 * (l & 3);
    #pragma unroll
    for (int f = 0; f < 2; f++) {
        int w1 = mbase + f * 16 + wo_l;
        int w2 = w1 + 8;
        #pragma unroll
        for (int nf = 0; nf < 8; nf++) {
            int oc = nf * 8 + oc_l;
            float b0 = bias_s[oc], b1 = bias_s[oc + 1];
            const float* c = acc[f][nf];
            if (w1 < HOUT) {
                out[obase + (size_t)oc * HWOUT + w1]       = c[0] + b0;
                out[obase + (size_t)(oc + 1) * HWOUT + w1] = c[1] + b1;
            }
            if (w2 < HOUT) {
                out[obase + (size_t)oc * HWOUT + w2]       = c[2] + b0;
                out[obase + (size_t)(oc + 1) * HWOUT + w2] = c[3] + b1;
            }
        }
    }
}

// ---------------- launch ----------------
extern "C" void kernel_launch(void* const* d_in, const int* in_sizes, int n_in,
                              void* d_out, int out_size) {
    const float* x      = (const float*)d_in[0];
    const float* fc1_w  = (const float*)d_in[1];
    const float* fc1_b  = (const float*)d_in[2];
    const float* fc2_w  = (const float*)d_in[3];
    const float* fc2_b  = (const float*)d_in[4];
    const float* weight = (const float*)d_in[5];
    const float* bias   = (const float*)d_in[6];
    float* out = (float*)d_out;

    const size_t WRET_ELEMS = (size_t)BATCH * DIM * KS * KS * DIM;  // 1,638,400
    float* wret = out + ((size_t)out_size - WRET_ELEMS);

    cudaFuncSetAttribute(conv_mma_kernel,
                         cudaFuncAttributeMaxDynamicSharedMemorySize, CONV_SMEM);

    zero_pool_kernel<<<1, BATCH * DIM>>>();
    transpose_pool_kernel<<<dim3(HW, BATCH), 256>>>(x);
    att_kernel<<<1, 256>>>(fc1_w, fc1_b, fc2_w, fc2_b, bias);
    aggw_kernel<<<dim3(DIM, BATCH), 256>>>(weight, wret);
    conv_mma_kernel<<<dim3(HOUT, BATCH), 128, CONV_SMEM>>>(out);
}